// round 2
// baseline (speedup 1.0000x reference)
#include <cuda_runtime.h>
#include <math.h>

#define TOK    4096
#define DIMN   2048
#define TRIPLE 6144
#define FFH    5632
#define NHEADS 16
#define HDIM   128
#define SEQL   2048

// ---------------- scratch (device globals: allocation-free) ----------------
__device__ float g_xn  [(size_t)TOK * DIMN];    // normed activations (reused)
__device__ float g_qkv [(size_t)TOK * TRIPLE];  // fused qkv
__device__ float g_attn[(size_t)TOK * DIMN];    // attention output
__device__ float g_x2  [(size_t)TOK * DIMN];    // after first residual
__device__ float g_h   [(size_t)TOK * FFH];     // gate, then silu(gate)*up

// ---------------- RMSNorm: one block per token ----------------
__global__ void __launch_bounds__(256) rmsnorm_kernel(const float* __restrict__ x,
                                                      const float* __restrict__ g,
                                                      float* __restrict__ o) {
    const int t = blockIdx.x;
    const float4* xr = reinterpret_cast<const float4*>(x) + (size_t)t * (DIMN / 4);
    float4* orow     = reinterpret_cast<float4*>(o) + (size_t)t * (DIMN / 4);
    const float4* g4 = reinterpret_cast<const float4*>(g);
    const int i0 = threadIdx.x, i1 = threadIdx.x + 256;
    const float4 v0 = xr[i0], v1 = xr[i1];
    float ss = v0.x*v0.x + v0.y*v0.y + v0.z*v0.z + v0.w*v0.w
             + v1.x*v1.x + v1.y*v1.y + v1.z*v1.z + v1.w*v1.w;
#pragma unroll
    for (int off = 16; off > 0; off >>= 1)
        ss += __shfl_xor_sync(0xffffffffu, ss, off);
    __shared__ float red[8];
    if ((threadIdx.x & 31) == 0) red[threadIdx.x >> 5] = ss;
    __syncthreads();
    const float tot = red[0]+red[1]+red[2]+red[3]+red[4]+red[5]+red[6]+red[7];
    const float r = rsqrtf(tot * (1.0f / DIMN) + 1e-6f);
    const float4 ga = g4[i0], gb = g4[i1];
    float4 o0, o1;
    o0.x = v0.x * r * ga.x; o0.y = v0.y * r * ga.y;
    o0.z = v0.z * r * ga.z; o0.w = v0.w * r * ga.w;
    o1.x = v1.x * r * gb.x; o1.y = v1.y * r * gb.y;
    o1.z = v1.z * r * gb.z; o1.w = v1.w * r * gb.w;
    orow[i0] = o0; orow[i1] = o1;
}

// ---------------- SGEMM: 128x128 block tile, K-tile 16, 8x8 microtile ----------------
// EPI: 0 = plain store, 1 = C = acc + aux, 2 = C = silu(aux) * acc (in-place OK)
template<int EPI>
__global__ void __launch_bounds__(256, 2)
gemm_kernel(const float* __restrict__ A, const float* __restrict__ B,
            float* __restrict__ C, const float* __restrict__ aux,
            int M, int N, int K)
{
    __shared__ float As[2][16][132];   // A tile transposed [k][m], padded
    __shared__ float Bs[2][16][128];   // B tile [k][n]
    const int tid = threadIdx.x;
    const int tx = tid & 15, ty = tid >> 4;
    const int bm = blockIdx.y << 7;
    const int bn = blockIdx.x << 7;

    const int arow = tid >> 2;   // 0..63 (rows 0..63 / 64..127)
    const int ak4  = tid & 3;    // 0..3 (k in steps of 4)
    const int brow = tid >> 5;   // 0..7 (rows 0..7 / 8..15)
    const int bc4  = tid & 31;   // 0..31

    const float* Ap0 = A + (size_t)(bm + arow) * K + ak4 * 4;
    const float* Ap1 = Ap0 + (size_t)64 * K;
    const float* Bp0 = B + (size_t)brow * N + bn + bc4 * 4;
    const float* Bp1 = Bp0 + (size_t)8 * N;

    float c[8][8];
#pragma unroll
    for (int i = 0; i < 8; ++i)
#pragma unroll
        for (int j = 0; j < 8; ++j) c[i][j] = 0.0f;

    // prologue: tile 0
    {
        const float4 a0 = *(const float4*)Ap0;
        const float4 a1 = *(const float4*)Ap1;
        const float4 b0 = *(const float4*)Bp0;
        const float4 b1 = *(const float4*)Bp1;
        As[0][ak4*4+0][arow]      = a0.x;
        As[0][ak4*4+1][arow]      = a0.y;
        As[0][ak4*4+2][arow]      = a0.z;
        As[0][ak4*4+3][arow]      = a0.w;
        As[0][ak4*4+0][arow+64]   = a1.x;
        As[0][ak4*4+1][arow+64]   = a1.y;
        As[0][ak4*4+2][arow+64]   = a1.z;
        As[0][ak4*4+3][arow+64]   = a1.w;
        *(float4*)&Bs[0][brow  ][bc4*4] = b0;
        *(float4*)&Bs[0][brow+8][bc4*4] = b1;
    }
    __syncthreads();

    const int nk = K >> 4;
    int buf = 0;
    for (int kt = 0; kt < nk; ++kt) {
        float4 na0, na1, nb0, nb1;
        const bool has = (kt + 1 < nk);
        if (has) {
            const int ko = (kt + 1) * 16;
            na0 = *(const float4*)(Ap0 + ko);
            na1 = *(const float4*)(Ap1 + ko);
            nb0 = *(const float4*)(Bp0 + (size_t)ko * N);
            nb1 = *(const float4*)(Bp1 + (size_t)ko * N);
        }
        const float (*Asl)[132] = As[buf];
        const float (*Bsl)[128] = Bs[buf];
#pragma unroll
        for (int kk = 0; kk < 16; ++kk) {
            const float4 x0 = *(const float4*)&Asl[kk][ty*8];
            const float4 x1 = *(const float4*)&Asl[kk][ty*8+4];
            const float4 y0 = *(const float4*)&Bsl[kk][tx*8];
            const float4 y1 = *(const float4*)&Bsl[kk][tx*8+4];
            const float av[8] = {x0.x,x0.y,x0.z,x0.w,x1.x,x1.y,x1.z,x1.w};
            const float bv[8] = {y0.x,y0.y,y0.z,y0.w,y1.x,y1.y,y1.z,y1.w};
#pragma unroll
            for (int i = 0; i < 8; ++i)
#pragma unroll
                for (int j = 0; j < 8; ++j)
                    c[i][j] += av[i] * bv[j];
        }
        if (has) {
            const int nb = buf ^ 1;
            As[nb][ak4*4+0][arow]    = na0.x;
            As[nb][ak4*4+1][arow]    = na0.y;
            As[nb][ak4*4+2][arow]    = na0.z;
            As[nb][ak4*4+3][arow]    = na0.w;
            As[nb][ak4*4+0][arow+64] = na1.x;
            As[nb][ak4*4+1][arow+64] = na1.y;
            As[nb][ak4*4+2][arow+64] = na1.z;
            As[nb][ak4*4+3][arow+64] = na1.w;
            *(float4*)&Bs[nb][brow  ][bc4*4] = nb0;
            *(float4*)&Bs[nb][brow+8][bc4*4] = nb1;
        }
        __syncthreads();
        buf ^= 1;
    }

    // epilogue
#pragma unroll
    for (int i = 0; i < 8; ++i) {
        const int row = bm + ty * 8 + i;
        const int col = bn + tx * 8;
        float* cp = C + (size_t)row * N + col;
#pragma unroll
        for (int j4 = 0; j4 < 2; ++j4) {
            float4 v = make_float4(c[i][j4*4+0], c[i][j4*4+1], c[i][j4*4+2], c[i][j4*4+3]);
            if (EPI == 1) {
                const float4 r = *(const float4*)(aux + (size_t)row * N + col + j4*4);
                v.x += r.x; v.y += r.y; v.z += r.z; v.w += r.w;
            } else if (EPI == 2) {
                const float4 gt = *(const float4*)(aux + (size_t)row * N + col + j4*4);
                v.x *= gt.x / (1.0f + __expf(-gt.x));
                v.y *= gt.y / (1.0f + __expf(-gt.y));
                v.z *= gt.z / (1.0f + __expf(-gt.z));
                v.w *= gt.w / (1.0f + __expf(-gt.w));
            }
            *(float4*)(cp + j4*4) = v;
        }
    }
}

// ---------------- Flash attention, fp32, BQ=BK=64, hd=128 ----------------
#define ATTN_SMEM ((64*128 + 64*132 + 64*128 + 64*68) * 4)

__global__ void __launch_bounds__(256)
attn_kernel(const float* __restrict__ qkv, float* __restrict__ out)
{
    extern __shared__ float sm[];
    float (*Qs)[128] = (float(*)[128])(sm);
    float (*Ks)[132] = (float(*)[132])(sm + 64*128);
    float (*Vs)[128] = (float(*)[128])(sm + 64*128 + 64*132);
    float (*Ps)[68]  = (float(*)[68]) (sm + 64*128 + 64*132 + 64*128);

    const int qt  = blockIdx.x;     // query tile within seq (0..31)
    const int h   = blockIdx.y;
    const int b   = blockIdx.z;
    const int tid = threadIdx.x;
    const int tx = tid & 15, ty = tid >> 4;
    const int tb   = b * SEQL + qt * 64;
    const int qcol = h * HDIM;
    const int kcol = DIMN + h * HDIM;
    const int vcol = 2 * DIMN + h * HDIM;

    // load Q tile
#pragma unroll
    for (int it = 0; it < 8; ++it) {
        const int f = tid + it * 256;
        const int row = f >> 5, c4 = f & 31;
        *(float4*)&Qs[row][c4*4] =
            *(const float4*)(qkv + (size_t)(tb + row) * TRIPLE + qcol + c4*4);
    }

    float m_i[4], l_i[4], acc[4][8];
#pragma unroll
    for (int i = 0; i < 4; ++i) {
        m_i[i] = -1e30f; l_i[i] = 0.0f;
#pragma unroll
        for (int d = 0; d < 8; ++d) acc[i][d] = 0.0f;
    }
    const float scale = 0.08838834764831845f;  // 1/sqrt(128)

    for (int kt = 0; kt <= qt; ++kt) {
        __syncthreads();  // prior tile fully consumed (and Q visible on kt==0)
        const int ktb = b * SEQL + kt * 64;
#pragma unroll
        for (int it = 0; it < 8; ++it) {
            const int f = tid + it * 256;
            const int row = f >> 5, c4 = f & 31;
            *(float4*)&Ks[row][c4*4] =
                *(const float4*)(qkv + (size_t)(ktb + row) * TRIPLE + kcol + c4*4);
            *(float4*)&Vs[row][c4*4] =
                *(const float4*)(qkv + (size_t)(ktb + row) * TRIPLE + vcol + c4*4);
        }
        __syncthreads();

        // S = Q K^T   (thread: rows ty*4+i, cols tx+16*j)
        float s[4][4];
#pragma unroll
        for (int i = 0; i < 4; ++i)
#pragma unroll
            for (int j = 0; j < 4; ++j) s[i][j] = 0.0f;

#pragma unroll 8
        for (int d4 = 0; d4 < 32; ++d4) {
            float4 qv[4], kv[4];
#pragma unroll
            for (int i = 0; i < 4; ++i) qv[i] = *(const float4*)&Qs[ty*4+i][d4*4];
#pragma unroll
            for (int j = 0; j < 4; ++j) kv[j] = *(const float4*)&Ks[tx+16*j][d4*4];
#pragma unroll
            for (int i = 0; i < 4; ++i)
#pragma unroll
                for (int j = 0; j < 4; ++j)
                    s[i][j] += qv[i].x*kv[j].x + qv[i].y*kv[j].y
                             + qv[i].z*kv[j].z + qv[i].w*kv[j].w;
        }

        const bool diag = (kt == qt);
#pragma unroll
        for (int i = 0; i < 4; ++i) {
            const int qg = qt * 64 + ty * 4 + i;
            float rm = -1e30f;
#pragma unroll
            for (int j = 0; j < 4; ++j) {
                s[i][j] *= scale;
                if (diag) {
                    const int kg = kt * 64 + tx + 16 * j;
                    if (kg > qg) s[i][j] = -1e30f;
                }
                rm = fmaxf(rm, s[i][j]);
            }
#pragma unroll
            for (int off = 8; off > 0; off >>= 1)
                rm = fmaxf(rm, __shfl_xor_sync(0xffffffffu, rm, off));
            const float mn = fmaxf(m_i[i], rm);
            const float corr = __expf(m_i[i] - mn);
            float rs = 0.0f;
#pragma unroll
            for (int j = 0; j < 4; ++j) {
                const float p = __expf(s[i][j] - mn);
                s[i][j] = p; rs += p;
            }
#pragma unroll
            for (int off = 8; off > 0; off >>= 1)
                rs += __shfl_xor_sync(0xffffffffu, rs, off);
            l_i[i] = l_i[i] * corr + rs;
            m_i[i] = mn;
#pragma unroll
            for (int d = 0; d < 8; ++d) acc[i][d] *= corr;
#pragma unroll
            for (int j = 0; j < 4; ++j) Ps[ty*4+i][tx+16*j] = s[i][j];
        }
        __syncthreads();

        // O += P V   (thread: rows ty*4+i, dims tx*8..tx*8+7)
#pragma unroll 8
        for (int k = 0; k < 64; ++k) {
            const float4 v0 = *(const float4*)&Vs[k][tx*8];
            const float4 v1 = *(const float4*)&Vs[k][tx*8+4];
#pragma unroll
            for (int i = 0; i < 4; ++i) {
                const float p = Ps[ty*4+i][k];
                acc[i][0] += p * v0.x; acc[i][1] += p * v0.y;
                acc[i][2] += p * v0.z; acc[i][3] += p * v0.w;
                acc[i][4] += p * v1.x; acc[i][5] += p * v1.y;
                acc[i][6] += p * v1.z; acc[i][7] += p * v1.w;
            }
        }
    }

#pragma unroll
    for (int i = 0; i < 4; ++i) {
        const float inv = 1.0f / l_i[i];
        const int row = tb + ty * 4 + i;
        float4 o0 = make_float4(acc[i][0]*inv, acc[i][1]*inv, acc[i][2]*inv, acc[i][3]*inv);
        float4 o1 = make_float4(acc[i][4]*inv, acc[i][5]*inv, acc[i][6]*inv, acc[i][7]*inv);
        *(float4*)(out + (size_t)row * DIMN + h*HDIM + tx*8)     = o0;
        *(float4*)(out + (size_t)row * DIMN + h*HDIM + tx*8 + 4) = o1;
    }
}

// ---------------- host ----------------
extern "C" void kernel_launch(void* const* d_in, const int* in_sizes, int n_in,
                              void* d_out, int out_size) {
    const float* x     = (const float*)d_in[0];
    const float* w_qkv = (const float*)d_in[1];
    const float* w_out = (const float*)d_in[2];
    const float* g1    = (const float*)d_in[3];
    const float* g2    = (const float*)d_in[4];
    const float* w1    = (const float*)d_in[5];
    const float* w3    = (const float*)d_in[6];
    const float* w2    = (const float*)d_in[7];
    float* out = (float*)d_out;
    (void)in_sizes; (void)n_in; (void)out_size;

    float *xn, *qkv, *attn, *x2, *hbuf;
    cudaGetSymbolAddress((void**)&xn,   g_xn);
    cudaGetSymbolAddress((void**)&qkv,  g_qkv);
    cudaGetSymbolAddress((void**)&attn, g_attn);
    cudaGetSymbolAddress((void**)&x2,   g_x2);
    cudaGetSymbolAddress((void**)&hbuf, g_h);

    cudaFuncSetAttribute(attn_kernel,
                         cudaFuncAttributeMaxDynamicSharedMemorySize, ATTN_SMEM);

    // x1 = rmsnorm(x, g1)
    rmsnorm_kernel<<<TOK, 256>>>(x, g1, xn);
    // qkv = x1 @ w_qkv
    gemm_kernel<0><<<dim3(TRIPLE/128, TOK/128), 256>>>(xn, w_qkv, qkv, nullptr, TOK, TRIPLE, DIMN);
    // attn = causal_flash_attention(qkv)
    attn_kernel<<<dim3(SEQL/64, NHEADS, 2), 256, ATTN_SMEM>>>(qkv, attn);
    // x2 = attn @ w_out + x
    gemm_kernel<1><<<dim3(DIMN/128, TOK/128), 256>>>(attn, w_out, x2, x, TOK, DIMN, DIMN);
    // xn = rmsnorm(x2, g2)
    rmsnorm_kernel<<<TOK, 256>>>(x2, g2, xn);
    // h = xn @ w1 (gate)
    gemm_kernel<0><<<dim3(FFH/128, TOK/128), 256>>>(xn, w1, hbuf, nullptr, TOK, FFH, DIMN);
    // h = silu(h) * (xn @ w3)   (in-place over gate buffer)
    gemm_kernel<2><<<dim3(FFH/128, TOK/128), 256>>>(xn, w3, hbuf, hbuf, TOK, FFH, DIMN);
    // out = h @ w2 + x2
    gemm_kernel<1><<<dim3(DIMN/128, TOK/128), 256>>>(hbuf, w2, out, x2, TOK, DIMN, FFH);
}

// round 4
// speedup vs baseline: 2.3205x; 2.3205x over previous
#include <cuda_runtime.h>
#include <math.h>
#include <stdint.h>

#define TOK    4096
#define DIMN   2048
#define TRIPLE 6144
#define FFH    5632
#define NHEADS 16
#define HDIM   128
#define SEQL   2048

// ---------------- scratch (device globals: allocation-free) ----------------
__device__ float g_xn    [(size_t)TOK * DIMN];
__device__ float g_qkv   [(size_t)TOK * TRIPLE];
__device__ float g_attn  [(size_t)TOK * DIMN];
__device__ float g_x2    [(size_t)TOK * DIMN];
__device__ float g_h     [(size_t)TOK * FFH];
// transposed + tf32-rounded weights [N, K]
__device__ float g_wtqkv [(size_t)TRIPLE * DIMN];
__device__ float g_wtout [(size_t)DIMN * DIMN];
__device__ float g_wt1   [(size_t)FFH * DIMN];
__device__ float g_wt3   [(size_t)FFH * DIMN];
__device__ float g_wt2   [(size_t)DIMN * FFH];

// ---------------- helpers ----------------
__device__ __forceinline__ uint32_t smem_u32(const void* p) {
    uint32_t a;
    asm("{ .reg .u64 t; cvta.to.shared.u64 t, %1; cvt.u32.u64 %0, t; }" : "=r"(a) : "l"(p));
    return a;
}
__device__ __forceinline__ float to_tf32(float v) {
    uint32_t r;
    asm("cvt.rna.tf32.f32 %0, %1;" : "=r"(r) : "f"(v));
    return __uint_as_float(r);
}

#define CP16(dst, src) \
    asm volatile("cp.async.cg.shared.global [%0], [%1], 16;" :: "r"(dst), "l"(src))
#define CP_COMMIT() asm volatile("cp.async.commit_group;" ::: "memory")
#define CP_WAIT1()  asm volatile("cp.async.wait_group 1;" ::: "memory")

__device__ __forceinline__ void mma_tf32(float& d0, float& d1, float& d2, float& d3,
                                         uint32_t a0, uint32_t a1, uint32_t a2, uint32_t a3,
                                         uint32_t b0, uint32_t b1) {
    asm volatile(
        "mma.sync.aligned.m16n8k8.row.col.f32.tf32.tf32.f32 "
        "{%0,%1,%2,%3}, {%4,%5,%6,%7}, {%8,%9}, {%0,%1,%2,%3};"
        : "+f"(d0), "+f"(d1), "+f"(d2), "+f"(d3)
        : "r"(a0), "r"(a1), "r"(a2), "r"(a3), "r"(b0), "r"(b1));
}

// ---------------- transpose + tf32 round: in [R, Ccols] -> out [Ccols, R] ----------------
__global__ void __launch_bounds__(256) transpose_round_kernel(const float* __restrict__ in,
                                                              float* __restrict__ out,
                                                              int R, int Ccols) {
    __shared__ float t[32][33];
    const int bx = blockIdx.x * 32;
    const int by = blockIdx.y * 32;
    const int x = threadIdx.x, y = threadIdx.y;
#pragma unroll
    for (int i = 0; i < 32; i += 8)
        t[y + i][x] = in[(size_t)(by + y + i) * Ccols + bx + x];
    __syncthreads();
#pragma unroll
    for (int i = 0; i < 32; i += 8)
        out[(size_t)(bx + y + i) * R + by + x] = to_tf32(t[x][y + i]);
}

// ---------------- RMSNorm (+ tf32 round on output) ----------------
__global__ void __launch_bounds__(256) rmsnorm_kernel(const float* __restrict__ x,
                                                      const float* __restrict__ g,
                                                      float* __restrict__ o) {
    const int t = blockIdx.x;
    const float4* xr = reinterpret_cast<const float4*>(x) + (size_t)t * (DIMN / 4);
    float4* orow     = reinterpret_cast<float4*>(o) + (size_t)t * (DIMN / 4);
    const float4* g4 = reinterpret_cast<const float4*>(g);
    const int i0 = threadIdx.x, i1 = threadIdx.x + 256;
    const float4 v0 = xr[i0], v1 = xr[i1];
    float ss = v0.x*v0.x + v0.y*v0.y + v0.z*v0.z + v0.w*v0.w
             + v1.x*v1.x + v1.y*v1.y + v1.z*v1.z + v1.w*v1.w;
#pragma unroll
    for (int off = 16; off > 0; off >>= 1)
        ss += __shfl_xor_sync(0xffffffffu, ss, off);
    __shared__ float red[8];
    if ((threadIdx.x & 31) == 0) red[threadIdx.x >> 5] = ss;
    __syncthreads();
    const float tot = red[0]+red[1]+red[2]+red[3]+red[4]+red[5]+red[6]+red[7];
    const float r = rsqrtf(tot * (1.0f / DIMN) + 1e-6f);
    const float4 ga = g4[i0], gb = g4[i1];
    float4 o0, o1;
    o0.x = to_tf32(v0.x * r * ga.x); o0.y = to_tf32(v0.y * r * ga.y);
    o0.z = to_tf32(v0.z * r * ga.z); o0.w = to_tf32(v0.w * r * ga.w);
    o1.x = to_tf32(v1.x * r * gb.x); o1.y = to_tf32(v1.y * r * gb.y);
    o1.z = to_tf32(v1.z * r * gb.z); o1.w = to_tf32(v1.w * r * gb.w);
    orow[i0] = o0; orow[i1] = o1;
}

// ---------------- tf32 mma.sync GEMM: C[M,N] = A[M,K] @ Bt[N,K]^T ----------------
#define BSTRIDE 36
#define KT 32
#define NSTAGE 3
#define STAGE_FLOATS (2 * 128 * BSTRIDE)
#define GEMM_SMEM_B (NSTAGE * STAGE_FLOATS * 4)

__device__ __forceinline__ void load_stage(float* st, const float* __restrict__ A,
                                           const float* __restrict__ Bt,
                                           int bm, int bn, int K, int kt, int tid) {
    float* as = st;
    float* bs = st + 128 * BSTRIDE;
#pragma unroll
    for (int t = 0; t < 4; ++t) {
        const int id = t * 256 + tid;
        const int row = id >> 3, c4 = id & 7;
        CP16(smem_u32(as + row * BSTRIDE + c4 * 4),
             A  + (size_t)(bm + row) * K + kt * KT + c4 * 4);
        CP16(smem_u32(bs + row * BSTRIDE + c4 * 4),
             Bt + (size_t)(bn + row) * K + kt * KT + c4 * 4);
    }
}

// EPI: 0 plain, 1 C=acc+aux, 2 C=to_tf32(silu(aux)*acc)
template<int EPI>
__global__ void __launch_bounds__(256, 1)
gemm_mma(const float* __restrict__ A, const float* __restrict__ Bt,
         float* __restrict__ C, const float* __restrict__ aux, int N, int K)
{
    extern __shared__ float smf[];
    const int tid = threadIdx.x, lane = tid & 31, wid = tid >> 5;
    const int bm = blockIdx.y << 7, bn = blockIdx.x << 7;
    const int wm = (wid >> 1) * 32, wn = (wid & 1) * 64;
    const int r = lane >> 2, c = lane & 3;

    float acc[2][8][4];
#pragma unroll
    for (int mi = 0; mi < 2; ++mi)
#pragma unroll
        for (int ni = 0; ni < 8; ++ni)
#pragma unroll
            for (int q = 0; q < 4; ++q) acc[mi][ni][q] = 0.0f;

    load_stage(smf, A, Bt, bm, bn, K, 0, tid); CP_COMMIT();
    load_stage(smf + STAGE_FLOATS, A, Bt, bm, bn, K, 1, tid); CP_COMMIT();

    const int nk = K / KT;
    for (int kt = 0; kt < nk; ++kt) {
        const int s = kt % NSTAGE;
        CP_WAIT1();
        __syncthreads();
        const int pf = kt + 2;
        if (pf < nk)
            load_stage(smf + (pf % NSTAGE) * STAGE_FLOATS, A, Bt, bm, bn, K, pf, tid);
        CP_COMMIT();

        const float* as = smf + s * STAGE_FLOATS;
        const float* bs = as + 128 * BSTRIDE;
#pragma unroll
        for (int k8 = 0; k8 < 4; ++k8) {
            const int kk = k8 * 8 + c;
            uint32_t a[2][4];
#pragma unroll
            for (int mi = 0; mi < 2; ++mi) {
                const float* ap = as + (wm + mi * 16) * BSTRIDE + kk;
                a[mi][0] = __float_as_uint(ap[r * BSTRIDE]);
                a[mi][1] = __float_as_uint(ap[(r + 8) * BSTRIDE]);
                a[mi][2] = __float_as_uint(ap[r * BSTRIDE + 4]);
                a[mi][3] = __float_as_uint(ap[(r + 8) * BSTRIDE + 4]);
            }
#pragma unroll
            for (int ni = 0; ni < 8; ++ni) {
                const float* bp = bs + (wn + ni * 8 + r) * BSTRIDE + kk;
                const uint32_t b0 = __float_as_uint(bp[0]);
                const uint32_t b1 = __float_as_uint(bp[4]);
                mma_tf32(acc[0][ni][0], acc[0][ni][1], acc[0][ni][2], acc[0][ni][3],
                         a[0][0], a[0][1], a[0][2], a[0][3], b0, b1);
                mma_tf32(acc[1][ni][0], acc[1][ni][1], acc[1][ni][2], acc[1][ni][3],
                         a[1][0], a[1][1], a[1][2], a[1][3], b0, b1);
            }
        }
    }

    // epilogue: thread owns (row, col..col+1) and (row+8, col..col+1) per frag
#pragma unroll
    for (int mi = 0; mi < 2; ++mi) {
#pragma unroll
        for (int ni = 0; ni < 8; ++ni) {
            const int row0 = bm + wm + mi * 16 + r;
            const int col  = bn + wn + ni * 8 + c * 2;
#pragma unroll
            for (int half = 0; half < 2; ++half) {
                const int row = row0 + half * 8;
                float vx = acc[mi][ni][half * 2 + 0];
                float vy = acc[mi][ni][half * 2 + 1];
                float* cp = C + (size_t)row * N + col;
                if (EPI == 1) {
                    const float2 a2 = *(const float2*)(aux + (size_t)row * N + col);
                    vx += a2.x; vy += a2.y;
                } else if (EPI == 2) {
                    const float2 g2 = *(const float2*)(aux + (size_t)row * N + col);
                    vx = to_tf32(vx * g2.x / (1.0f + __expf(-g2.x)));
                    vy = to_tf32(vy * g2.y / (1.0f + __expf(-g2.y)));
                }
                *(float2*)cp = make_float2(vx, vy);
            }
        }
    }
}

// ---------------- Flash attention, fp32, BQ=BK=64, hd=128 ----------------
#define ATTN_SMEM ((64*128 + 64*132 + 64*128 + 64*68) * 4)

__global__ void __launch_bounds__(256)
attn_kernel(const float* __restrict__ qkv, float* __restrict__ out)
{
    extern __shared__ float sm[];
    float (*Qs)[128] = (float(*)[128])(sm);
    float (*Ks)[132] = (float(*)[132])(sm + 64*128);
    float (*Vs)[128] = (float(*)[128])(sm + 64*128 + 64*132);
    float (*Ps)[68]  = (float(*)[68]) (sm + 64*128 + 64*132 + 64*128);

    const int qt  = blockIdx.x;
    const int h   = blockIdx.y;
    const int b   = blockIdx.z;
    const int tid = threadIdx.x;
    const int tx = tid & 15, ty = tid >> 4;
    const int tb   = b * SEQL + qt * 64;
    const int qcol = h * HDIM;
    const int kcol = DIMN + h * HDIM;
    const int vcol = 2 * DIMN + h * HDIM;

#pragma unroll
    for (int it = 0; it < 8; ++it) {
        const int f = tid + it * 256;
        const int row = f >> 5, c4 = f & 31;
        *(float4*)&Qs[row][c4*4] =
            *(const float4*)(qkv + (size_t)(tb + row) * TRIPLE + qcol + c4*4);
    }

    float m_i[4], l_i[4], acc[4][8];
#pragma unroll
    for (int i = 0; i < 4; ++i) {
        m_i[i] = -1e30f; l_i[i] = 0.0f;
#pragma unroll
        for (int d = 0; d < 8; ++d) acc[i][d] = 0.0f;
    }
    const float scale = 0.08838834764831845f;

    for (int kt = 0; kt <= qt; ++kt) {
        __syncthreads();
        const int ktb = b * SEQL + kt * 64;
#pragma unroll
        for (int it = 0; it < 8; ++it) {
            const int f = tid + it * 256;
            const int row = f >> 5, c4 = f & 31;
            *(float4*)&Ks[row][c4*4] =
                *(const float4*)(qkv + (size_t)(ktb + row) * TRIPLE + kcol + c4*4);
            *(float4*)&Vs[row][c4*4] =
                *(const float4*)(qkv + (size_t)(ktb + row) * TRIPLE + vcol + c4*4);
        }
        __syncthreads();

        float s[4][4];
#pragma unroll
        for (int i = 0; i < 4; ++i)
#pragma unroll
            for (int j = 0; j < 4; ++j) s[i][j] = 0.0f;

#pragma unroll 8
        for (int d4 = 0; d4 < 32; ++d4) {
            float4 qv[4], kv[4];
#pragma unroll
            for (int i = 0; i < 4; ++i) qv[i] = *(const float4*)&Qs[ty*4+i][d4*4];
#pragma unroll
            for (int j = 0; j < 4; ++j) kv[j] = *(const float4*)&Ks[tx+16*j][d4*4];
#pragma unroll
            for (int i = 0; i < 4; ++i)
#pragma unroll
                for (int j = 0; j < 4; ++j)
                    s[i][j] += qv[i].x*kv[j].x + qv[i].y*kv[j].y
                             + qv[i].z*kv[j].z + qv[i].w*kv[j].w;
        }

        const bool diag = (kt == qt);
#pragma unroll
        for (int i = 0; i < 4; ++i) {
            const int qg = qt * 64 + ty * 4 + i;
            float rm = -1e30f;
#pragma unroll
            for (int j = 0; j < 4; ++j) {
                s[i][j] *= scale;
                if (diag) {
                    const int kg = kt * 64 + tx + 16 * j;
                    if (kg > qg) s[i][j] = -1e30f;
                }
                rm = fmaxf(rm, s[i][j]);
            }
#pragma unroll
            for (int off = 8; off > 0; off >>= 1)
                rm = fmaxf(rm, __shfl_xor_sync(0xffffffffu, rm, off));
            const float mn = fmaxf(m_i[i], rm);
            const float corr = __expf(m_i[i] - mn);
            float rs = 0.0f;
#pragma unroll
            for (int j = 0; j < 4; ++j) {
                const float p = __expf(s[i][j] - mn);
                s[i][j] = p; rs += p;
            }
#pragma unroll
            for (int off = 8; off > 0; off >>= 1)
                rs += __shfl_xor_sync(0xffffffffu, rs, off);
            l_i[i] = l_i[i] * corr + rs;
            m_i[i] = mn;
#pragma unroll
            for (int d = 0; d < 8; ++d) acc[i][d] *= corr;
#pragma unroll
            for (int j = 0; j < 4; ++j) Ps[ty*4+i][tx+16*j] = s[i][j];
        }
        __syncthreads();

#pragma unroll 8
        for (int k = 0; k < 64; ++k) {
            const float4 v0 = *(const float4*)&Vs[k][tx*8];
            const float4 v1 = *(const float4*)&Vs[k][tx*8+4];
#pragma unroll
            for (int i = 0; i < 4; ++i) {
                const float p = Ps[ty*4+i][k];
                acc[i][0] += p * v0.x; acc[i][1] += p * v0.y;
                acc[i][2] += p * v0.z; acc[i][3] += p * v0.w;
                acc[i][4] += p * v1.x; acc[i][5] += p * v1.y;
                acc[i][6] += p * v1.z; acc[i][7] += p * v1.w;
            }
        }
    }

#pragma unroll
    for (int i = 0; i < 4; ++i) {
        const float inv = 1.0f / l_i[i];
        const int row = tb + ty * 4 + i;
        float4 o0 = make_float4(to_tf32(acc[i][0]*inv), to_tf32(acc[i][1]*inv),
                                to_tf32(acc[i][2]*inv), to_tf32(acc[i][3]*inv));
        float4 o1 = make_float4(to_tf32(acc[i][4]*inv), to_tf32(acc[i][5]*inv),
                                to_tf32(acc[i][6]*inv), to_tf32(acc[i][7]*inv));
        *(float4*)(out + (size_t)row * DIMN + h*HDIM + tx*8)     = o0;
        *(float4*)(out + (size_t)row * DIMN + h*HDIM + tx*8 + 4) = o1;
    }
}

// ---------------- host ----------------
extern "C" void kernel_launch(void* const* d_in, const int* in_sizes, int n_in,
                              void* d_out, int out_size) {
    const float* x     = (const float*)d_in[0];
    const float* w_qkv = (const float*)d_in[1];
    const float* w_out = (const float*)d_in[2];
    const float* g1    = (const float*)d_in[3];
    const float* g2    = (const float*)d_in[4];
    const float* w1    = (const float*)d_in[5];
    const float* w3    = (const float*)d_in[6];
    const float* w2    = (const float*)d_in[7];
    float* out = (float*)d_out;
    (void)in_sizes; (void)n_in; (void)out_size;

    float *xn, *qkv, *attn, *x2, *hbuf;
    float *wtqkv, *wtout, *wt1, *wt3, *wt2;
    cudaGetSymbolAddress((void**)&xn,    g_xn);
    cudaGetSymbolAddress((void**)&qkv,   g_qkv);
    cudaGetSymbolAddress((void**)&attn,  g_attn);
    cudaGetSymbolAddress((void**)&x2,    g_x2);
    cudaGetSymbolAddress((void**)&hbuf,  g_h);
    cudaGetSymbolAddress((void**)&wtqkv, g_wtqkv);
    cudaGetSymbolAddress((void**)&wtout, g_wtout);
    cudaGetSymbolAddress((void**)&wt1,   g_wt1);
    cudaGetSymbolAddress((void**)&wt3,   g_wt3);
    cudaGetSymbolAddress((void**)&wt2,   g_wt2);

    cudaFuncSetAttribute(attn_kernel,
                         cudaFuncAttributeMaxDynamicSharedMemorySize, ATTN_SMEM);
    cudaFuncSetAttribute(gemm_mma<0>,
                         cudaFuncAttributeMaxDynamicSharedMemorySize, GEMM_SMEM_B);
    cudaFuncSetAttribute(gemm_mma<1>,
                         cudaFuncAttributeMaxDynamicSharedMemorySize, GEMM_SMEM_B);
    cudaFuncSetAttribute(gemm_mma<2>,
                         cudaFuncAttributeMaxDynamicSharedMemorySize, GEMM_SMEM_B);

    const dim3 tb(32, 8);
    transpose_round_kernel<<<dim3(TRIPLE/32, DIMN/32), tb>>>(w_qkv, wtqkv, DIMN, TRIPLE);
    transpose_round_kernel<<<dim3(DIMN/32,  DIMN/32), tb>>>(w_out, wtout, DIMN, DIMN);
    transpose_round_kernel<<<dim3(FFH/32,   DIMN/32), tb>>>(w1,    wt1,   DIMN, FFH);
    transpose_round_kernel<<<dim3(FFH/32,   DIMN/32), tb>>>(w3,    wt3,   DIMN, FFH);
    transpose_round_kernel<<<dim3(DIMN/32,  FFH/32),  tb>>>(w2,    wt2,   FFH,  DIMN);

    rmsnorm_kernel<<<TOK, 256>>>(x, g1, xn);
    gemm_mma<0><<<dim3(TRIPLE/128, TOK/128), 256, GEMM_SMEM_B>>>(xn, wtqkv, qkv, qkv, TRIPLE, DIMN);
    attn_kernel<<<dim3(SEQL/64, NHEADS, 2), 256, ATTN_SMEM>>>(qkv, attn);
    gemm_mma<1><<<dim3(DIMN/128, TOK/128), 256, GEMM_SMEM_B>>>(attn, wtout, x2, x, DIMN, DIMN);
    rmsnorm_kernel<<<TOK, 256>>>(x2, g2, xn);
    gemm_mma<0><<<dim3(FFH/128, TOK/128), 256, GEMM_SMEM_B>>>(xn, wt1, hbuf, hbuf, FFH, DIMN);
    gemm_mma<2><<<dim3(FFH/128, TOK/128), 256, GEMM_SMEM_B>>>(xn, wt3, hbuf, hbuf, FFH, DIMN);
    gemm_mma<1><<<dim3(DIMN/128, TOK/128), 256, GEMM_SMEM_B>>>(hbuf, wt2, out, x2, DIMN, FFH);
}

// round 5
// speedup vs baseline: 2.8715x; 1.2374x over previous
#include <cuda_runtime.h>
#include <math.h>
#include <stdint.h>

#define TOK    4096
#define DIMN   2048
#define TRIPLE 6144
#define FFH    5632
#define NHEADS 16
#define HDIM   128
#define SEQL   2048

// ---------------- scratch (device globals: allocation-free) ----------------
__device__ float g_xn    [(size_t)TOK * DIMN];
__device__ float g_qkv   [(size_t)TOK * TRIPLE];
__device__ float g_attn  [(size_t)TOK * DIMN];
__device__ float g_x2    [(size_t)TOK * DIMN];
__device__ float g_h     [(size_t)TOK * FFH];
// transposed + tf32-rounded weights [N, K]
__device__ float g_wtqkv [(size_t)TRIPLE * DIMN];
__device__ float g_wtout [(size_t)DIMN * DIMN];
__device__ float g_wt1   [(size_t)FFH * DIMN];
__device__ float g_wt3   [(size_t)FFH * DIMN];
__device__ float g_wt2   [(size_t)DIMN * FFH];

// ---------------- helpers ----------------
__device__ __forceinline__ uint32_t smem_u32(const void* p) {
    uint32_t a;
    asm("{ .reg .u64 t; cvta.to.shared.u64 t, %1; cvt.u32.u64 %0, t; }" : "=r"(a) : "l"(p));
    return a;
}
__device__ __forceinline__ float to_tf32(float v) {
    uint32_t r;
    asm("cvt.rna.tf32.f32 %0, %1;" : "=r"(r) : "f"(v));
    return __uint_as_float(r);
}

#define CP16(dst, src) \
    asm volatile("cp.async.cg.shared.global [%0], [%1], 16;" :: "r"(dst), "l"(src))
#define CP_COMMIT() asm volatile("cp.async.commit_group;" ::: "memory")
#define CP_WAIT1()  asm volatile("cp.async.wait_group 1;" ::: "memory")

__device__ __forceinline__ void mma_tf32(float& d0, float& d1, float& d2, float& d3,
                                         uint32_t a0, uint32_t a1, uint32_t a2, uint32_t a3,
                                         uint32_t b0, uint32_t b1) {
    asm volatile(
        "mma.sync.aligned.m16n8k8.row.col.f32.tf32.tf32.f32 "
        "{%0,%1,%2,%3}, {%4,%5,%6,%7}, {%8,%9}, {%0,%1,%2,%3};"
        : "+f"(d0), "+f"(d1), "+f"(d2), "+f"(d3)
        : "r"(a0), "r"(a1), "r"(a2), "r"(a3), "r"(b0), "r"(b1));
}

// ---------------- transpose + tf32 round: in [R, Ccols] -> out [Ccols, R] ----------------
__global__ void __launch_bounds__(256) transpose_round_kernel(const float* __restrict__ in,
                                                              float* __restrict__ out,
                                                              int R, int Ccols) {
    __shared__ float t[32][33];
    const int bx = blockIdx.x * 32;
    const int by = blockIdx.y * 32;
    const int x = threadIdx.x, y = threadIdx.y;
#pragma unroll
    for (int i = 0; i < 32; i += 8)
        t[y + i][x] = in[(size_t)(by + y + i) * Ccols + bx + x];
    __syncthreads();
#pragma unroll
    for (int i = 0; i < 32; i += 8)
        out[(size_t)(bx + y + i) * R + by + x] = to_tf32(t[x][y + i]);
}

// ---------------- RMSNorm (+ tf32 round on output) ----------------
__global__ void __launch_bounds__(256) rmsnorm_kernel(const float* __restrict__ x,
                                                      const float* __restrict__ g,
                                                      float* __restrict__ o) {
    const int t = blockIdx.x;
    const float4* xr = reinterpret_cast<const float4*>(x) + (size_t)t * (DIMN / 4);
    float4* orow     = reinterpret_cast<float4*>(o) + (size_t)t * (DIMN / 4);
    const float4* g4 = reinterpret_cast<const float4*>(g);
    const int i0 = threadIdx.x, i1 = threadIdx.x + 256;
    const float4 v0 = xr[i0], v1 = xr[i1];
    float ss = v0.x*v0.x + v0.y*v0.y + v0.z*v0.z + v0.w*v0.w
             + v1.x*v1.x + v1.y*v1.y + v1.z*v1.z + v1.w*v1.w;
#pragma unroll
    for (int off = 16; off > 0; off >>= 1)
        ss += __shfl_xor_sync(0xffffffffu, ss, off);
    __shared__ float red[8];
    if ((threadIdx.x & 31) == 0) red[threadIdx.x >> 5] = ss;
    __syncthreads();
    const float tot = red[0]+red[1]+red[2]+red[3]+red[4]+red[5]+red[6]+red[7];
    const float r = rsqrtf(tot * (1.0f / DIMN) + 1e-6f);
    const float4 ga = g4[i0], gb = g4[i1];
    float4 o0, o1;
    o0.x = to_tf32(v0.x * r * ga.x); o0.y = to_tf32(v0.y * r * ga.y);
    o0.z = to_tf32(v0.z * r * ga.z); o0.w = to_tf32(v0.w * r * ga.w);
    o1.x = to_tf32(v1.x * r * gb.x); o1.y = to_tf32(v1.y * r * gb.y);
    o1.z = to_tf32(v1.z * r * gb.z); o1.w = to_tf32(v1.w * r * gb.w);
    orow[i0] = o0; orow[i1] = o1;
}

// ---------------- tf32 mma.sync GEMM: C[M,N] = A[M,K] @ Bt[N,K]^T ----------------
#define BSTRIDE 36
#define KT 32
#define NSTAGE 3
#define STAGE_FLOATS (2 * 128 * BSTRIDE)
#define GEMM_SMEM_B (NSTAGE * STAGE_FLOATS * 4)

__device__ __forceinline__ void load_stage(float* st, const float* __restrict__ A,
                                           const float* __restrict__ Bt,
                                           int bm, int bn, int K, int kt, int tid) {
    float* as = st;
    float* bs = st + 128 * BSTRIDE;
#pragma unroll
    for (int t = 0; t < 4; ++t) {
        const int id = t * 256 + tid;
        const int row = id >> 3, c4 = id & 7;
        CP16(smem_u32(as + row * BSTRIDE + c4 * 4),
             A  + (size_t)(bm + row) * K + kt * KT + c4 * 4);
        CP16(smem_u32(bs + row * BSTRIDE + c4 * 4),
             Bt + (size_t)(bn + row) * K + kt * KT + c4 * 4);
    }
}

// EPI: 0 plain, 1 C=acc+aux, 2 C=to_tf32(silu(aux)*acc), 3 C=to_tf32(acc)
template<int EPI>
__global__ void __launch_bounds__(256, 1)
gemm_mma(const float* __restrict__ A, const float* __restrict__ Bt,
         float* __restrict__ C, const float* __restrict__ aux, int N, int K)
{
    extern __shared__ float smf[];
    const int tid = threadIdx.x, lane = tid & 31, wid = tid >> 5;
    const int bm = blockIdx.y << 7, bn = blockIdx.x << 7;
    const int wm = (wid >> 1) * 32, wn = (wid & 1) * 64;
    const int r = lane >> 2, c = lane & 3;

    float acc[2][8][4];
#pragma unroll
    for (int mi = 0; mi < 2; ++mi)
#pragma unroll
        for (int ni = 0; ni < 8; ++ni)
#pragma unroll
            for (int q = 0; q < 4; ++q) acc[mi][ni][q] = 0.0f;

    load_stage(smf, A, Bt, bm, bn, K, 0, tid); CP_COMMIT();
    load_stage(smf + STAGE_FLOATS, A, Bt, bm, bn, K, 1, tid); CP_COMMIT();

    const int nk = K / KT;
    for (int kt = 0; kt < nk; ++kt) {
        const int s = kt % NSTAGE;
        CP_WAIT1();
        __syncthreads();
        const int pf = kt + 2;
        if (pf < nk)
            load_stage(smf + (pf % NSTAGE) * STAGE_FLOATS, A, Bt, bm, bn, K, pf, tid);
        CP_COMMIT();

        const float* as = smf + s * STAGE_FLOATS;
        const float* bs = as + 128 * BSTRIDE;
#pragma unroll
        for (int k8 = 0; k8 < 4; ++k8) {
            const int kk = k8 * 8 + c;
            uint32_t a[2][4];
#pragma unroll
            for (int mi = 0; mi < 2; ++mi) {
                const float* ap = as + (wm + mi * 16) * BSTRIDE + kk;
                a[mi][0] = __float_as_uint(ap[r * BSTRIDE]);
                a[mi][1] = __float_as_uint(ap[(r + 8) * BSTRIDE]);
                a[mi][2] = __float_as_uint(ap[r * BSTRIDE + 4]);
                a[mi][3] = __float_as_uint(ap[(r + 8) * BSTRIDE + 4]);
            }
#pragma unroll
            for (int ni = 0; ni < 8; ++ni) {
                const float* bp = bs + (wn + ni * 8 + r) * BSTRIDE + kk;
                const uint32_t b0 = __float_as_uint(bp[0]);
                const uint32_t b1 = __float_as_uint(bp[4]);
                mma_tf32(acc[0][ni][0], acc[0][ni][1], acc[0][ni][2], acc[0][ni][3],
                         a[0][0], a[0][1], a[0][2], a[0][3], b0, b1);
                mma_tf32(acc[1][ni][0], acc[1][ni][1], acc[1][ni][2], acc[1][ni][3],
                         a[1][0], a[1][1], a[1][2], a[1][3], b0, b1);
            }
        }
    }

#pragma unroll
    for (int mi = 0; mi < 2; ++mi) {
#pragma unroll
        for (int ni = 0; ni < 8; ++ni) {
            const int row0 = bm + wm + mi * 16 + r;
            const int col  = bn + wn + ni * 8 + c * 2;
#pragma unroll
            for (int half = 0; half < 2; ++half) {
                const int row = row0 + half * 8;
                float vx = acc[mi][ni][half * 2 + 0];
                float vy = acc[mi][ni][half * 2 + 1];
                float* cp = C + (size_t)row * N + col;
                if (EPI == 1) {
                    const float2 a2 = *(const float2*)(aux + (size_t)row * N + col);
                    vx += a2.x; vy += a2.y;
                } else if (EPI == 2) {
                    const float2 g2 = *(const float2*)(aux + (size_t)row * N + col);
                    vx = to_tf32(vx * g2.x / (1.0f + __expf(-g2.x)));
                    vy = to_tf32(vy * g2.y / (1.0f + __expf(-g2.y)));
                } else if (EPI == 3) {
                    vx = to_tf32(vx); vy = to_tf32(vy);
                }
                *(float2*)cp = make_float2(vx, vy);
            }
        }
    }
}

// ---------------- Flash attention on tensor cores (tf32 mma) ----------------
// BQ=128, BKV=64, HD=128, 8 warps (each owns 16 q-rows)
#define QS_OFF 0
#define QS_STR 132
#define KS_OFF (128 * 132)
#define KS_STR 132
#define VT_OFF (KS_OFF + 64 * 132)
#define PS_OFF (VT_OFF + 128 * 64)
#define PS_STR 68
#define ATTN_SMEM ((PS_OFF + 128 * 68) * 4)

__device__ __forceinline__ int vt_idx(int n, int k) {
    return VT_OFF + n * 64 + (k ^ ((n & 7) << 2) ^ ((n >> 3) & 3));
}

__global__ void __launch_bounds__(256, 1)
attn_mma(const float* __restrict__ qkv, float* __restrict__ out)
{
    extern __shared__ float sm[];
    const int qt = blockIdx.x, h = blockIdx.y, b = blockIdx.z;
    const int tid = threadIdx.x, lane = tid & 31, wid = tid >> 5;
    const int r = lane >> 2, c = lane & 3;
    const int q0 = qt * 128;
    const int tb = b * SEQL + q0;
    const int wq = wid * 16;
    const int qcol = h * HDIM, kcol = DIMN + h * HDIM, vcol = 2 * DIMN + h * HDIM;
    const float scale = 0.08838834764831845f;  // 1/sqrt(128)

    // load Q tile [128][128] -> Qs (16 iters of float4)
#pragma unroll
    for (int it = 0; it < 16; ++it) {
        const int idx = it * 256 + tid;
        const int row = idx >> 5, c4 = idx & 31;
        *(float4*)&sm[QS_OFF + row * QS_STR + c4 * 4] =
            *(const float4*)(qkv + (size_t)(tb + row) * TRIPLE + qcol + c4 * 4);
    }

    float m[2] = {-1e30f, -1e30f}, l[2] = {0.0f, 0.0f};
    float acc[16][4];
#pragma unroll
    for (int nt = 0; nt < 16; ++nt)
#pragma unroll
        for (int q = 0; q < 4; ++q) acc[nt][q] = 0.0f;

    const int nkv = 2 * qt + 2;
    for (int kt = 0; kt < nkv; ++kt) {
        __syncthreads();   // Ps consumed / Qs visible on first iter
        const int kb = b * SEQL + kt * 64;
        // K tile [64][128] -> Ks
#pragma unroll
        for (int it = 0; it < 8; ++it) {
            const int idx = it * 256 + tid;
            const int row = idx >> 5, c4 = idx & 31;
            *(float4*)&sm[KS_OFF + row * KS_STR + c4 * 4] =
                *(const float4*)(qkv + (size_t)(kb + row) * TRIPLE + kcol + c4 * 4);
        }
        // V tile transposed -> Vt (swizzled)
#pragma unroll
        for (int it = 0; it < 8; ++it) {
            const int idx = it * 256 + tid;
            const int row = idx >> 5, c4 = idx & 31;
            const float4 v = *(const float4*)(qkv + (size_t)(kb + row) * TRIPLE + vcol + c4 * 4);
            sm[vt_idx(c4 * 4 + 0, row)] = v.x;
            sm[vt_idx(c4 * 4 + 1, row)] = v.y;
            sm[vt_idx(c4 * 4 + 2, row)] = v.z;
            sm[vt_idx(c4 * 4 + 3, row)] = v.w;
        }
        __syncthreads();

        // ---- S = Q K^T (warp: 16x64, K=128) ----
        float s[8][4];
#pragma unroll
        for (int nt = 0; nt < 8; ++nt)
#pragma unroll
            for (int q = 0; q < 4; ++q) s[nt][q] = 0.0f;
#pragma unroll
        for (int k8 = 0; k8 < 16; ++k8) {
            const int kk = k8 * 8 + c;
            const float* ap = sm + QS_OFF + (wq + r) * QS_STR + kk;
            const uint32_t a0 = __float_as_uint(ap[0]);
            const uint32_t a1 = __float_as_uint(ap[8 * QS_STR]);
            const uint32_t a2 = __float_as_uint(ap[4]);
            const uint32_t a3 = __float_as_uint(ap[8 * QS_STR + 4]);
#pragma unroll
            for (int nt = 0; nt < 8; ++nt) {
                const float* bp = sm + KS_OFF + (nt * 8 + r) * KS_STR + kk;
                mma_tf32(s[nt][0], s[nt][1], s[nt][2], s[nt][3],
                         a0, a1, a2, a3,
                         __float_as_uint(bp[0]), __float_as_uint(bp[4]));
            }
        }

        // ---- online softmax ----
        const bool diag = (kt >= 2 * qt);
#pragma unroll
        for (int half = 0; half < 2; ++half) {
            const int qg = q0 + wq + r + 8 * half;
            float rm = -1e30f;
#pragma unroll
            for (int nt = 0; nt < 8; ++nt)
#pragma unroll
                for (int q2 = 0; q2 < 2; ++q2) {
                    float v = s[nt][2 * half + q2] * scale;
                    if (diag && (kt * 64 + nt * 8 + 2 * c + q2 > qg)) v = -1e30f;
                    s[nt][2 * half + q2] = v;
                    rm = fmaxf(rm, v);
                }
            rm = fmaxf(rm, __shfl_xor_sync(0xffffffffu, rm, 1));
            rm = fmaxf(rm, __shfl_xor_sync(0xffffffffu, rm, 2));
            const float mn = fmaxf(m[half], rm);
            const float corr = __expf(m[half] - mn);
            float rs = 0.0f;
#pragma unroll
            for (int nt = 0; nt < 8; ++nt)
#pragma unroll
                for (int q2 = 0; q2 < 2; ++q2) {
                    const float p = __expf(s[nt][2 * half + q2] - mn);
                    s[nt][2 * half + q2] = p;
                    rs += p;
                }
            rs += __shfl_xor_sync(0xffffffffu, rs, 1);
            rs += __shfl_xor_sync(0xffffffffu, rs, 2);
            l[half] = l[half] * corr + rs;
            m[half] = mn;
#pragma unroll
            for (int nt = 0; nt < 16; ++nt) {
                acc[nt][2 * half + 0] *= corr;
                acc[nt][2 * half + 1] *= corr;
            }
            // store P (tf32-rounded) for PV mma
#pragma unroll
            for (int nt = 0; nt < 8; ++nt)
                *(float2*)&sm[PS_OFF + (wq + r + 8 * half) * PS_STR + nt * 8 + 2 * c] =
                    make_float2(to_tf32(s[nt][2 * half + 0]), to_tf32(s[nt][2 * half + 1]));
        }
        __syncwarp();

        // ---- O += P V (warp: 16x128, K=64) ----
#pragma unroll
        for (int k8 = 0; k8 < 8; ++k8) {
            const int kk = k8 * 8 + c;
            const float* ap = sm + PS_OFF + (wq + r) * PS_STR + kk;
            const uint32_t a0 = __float_as_uint(ap[0]);
            const uint32_t a1 = __float_as_uint(ap[8 * PS_STR]);
            const uint32_t a2 = __float_as_uint(ap[4]);
            const uint32_t a3 = __float_as_uint(ap[8 * PS_STR + 4]);
#pragma unroll
            for (int nt = 0; nt < 16; ++nt) {
                const uint32_t b0 = __float_as_uint(sm[vt_idx(nt * 8 + r, kk)]);
                const uint32_t b1 = __float_as_uint(sm[vt_idx(nt * 8 + r, kk + 4)]);
                mma_tf32(acc[nt][0], acc[nt][1], acc[nt][2], acc[nt][3],
                         a0, a1, a2, a3, b0, b1);
            }
        }
    }

    // ---- write O (tf32-rounded; feeds w_out GEMM) ----
#pragma unroll
    for (int half = 0; half < 2; ++half) {
        const float inv = 1.0f / l[half];
        const int row = tb + wq + r + 8 * half;
#pragma unroll
        for (int nt = 0; nt < 16; ++nt) {
            const int col = h * HDIM + nt * 8 + 2 * c;
            *(float2*)(out + (size_t)row * DIMN + col) =
                make_float2(to_tf32(acc[nt][2 * half + 0] * inv),
                            to_tf32(acc[nt][2 * half + 1] * inv));
        }
    }
}

// ---------------- host ----------------
extern "C" void kernel_launch(void* const* d_in, const int* in_sizes, int n_in,
                              void* d_out, int out_size) {
    const float* x     = (const float*)d_in[0];
    const float* w_qkv = (const float*)d_in[1];
    const float* w_out = (const float*)d_in[2];
    const float* g1    = (const float*)d_in[3];
    const float* g2    = (const float*)d_in[4];
    const float* w1    = (const float*)d_in[5];
    const float* w3    = (const float*)d_in[6];
    const float* w2    = (const float*)d_in[7];
    float* out = (float*)d_out;
    (void)in_sizes; (void)n_in; (void)out_size;

    float *xn, *qkv, *attn, *x2, *hbuf;
    float *wtqkv, *wtout, *wt1, *wt3, *wt2;
    cudaGetSymbolAddress((void**)&xn,    g_xn);
    cudaGetSymbolAddress((void**)&qkv,   g_qkv);
    cudaGetSymbolAddress((void**)&attn,  g_attn);
    cudaGetSymbolAddress((void**)&x2,    g_x2);
    cudaGetSymbolAddress((void**)&hbuf,  g_h);
    cudaGetSymbolAddress((void**)&wtqkv, g_wtqkv);
    cudaGetSymbolAddress((void**)&wtout, g_wtout);
    cudaGetSymbolAddress((void**)&wt1,   g_wt1);
    cudaGetSymbolAddress((void**)&wt3,   g_wt3);
    cudaGetSymbolAddress((void**)&wt2,   g_wt2);

    cudaFuncSetAttribute(attn_mma,
                         cudaFuncAttributeMaxDynamicSharedMemorySize, ATTN_SMEM);
    cudaFuncSetAttribute(gemm_mma<0>,
                         cudaFuncAttributeMaxDynamicSharedMemorySize, GEMM_SMEM_B);
    cudaFuncSetAttribute(gemm_mma<1>,
                         cudaFuncAttributeMaxDynamicSharedMemorySize, GEMM_SMEM_B);
    cudaFuncSetAttribute(gemm_mma<2>,
                         cudaFuncAttributeMaxDynamicSharedMemorySize, GEMM_SMEM_B);
    cudaFuncSetAttribute(gemm_mma<3>,
                         cudaFuncAttributeMaxDynamicSharedMemorySize, GEMM_SMEM_B);

    const dim3 tb(32, 8);
    transpose_round_kernel<<<dim3(TRIPLE/32, DIMN/32), tb>>>(w_qkv, wtqkv, DIMN, TRIPLE);
    transpose_round_kernel<<<dim3(DIMN/32,  DIMN/32), tb>>>(w_out, wtout, DIMN, DIMN);
    transpose_round_kernel<<<dim3(FFH/32,   DIMN/32), tb>>>(w1,    wt1,   DIMN, FFH);
    transpose_round_kernel<<<dim3(FFH/32,   DIMN/32), tb>>>(w3,    wt3,   DIMN, FFH);
    transpose_round_kernel<<<dim3(DIMN/32,  FFH/32),  tb>>>(w2,    wt2,   FFH,  DIMN);

    rmsnorm_kernel<<<TOK, 256>>>(x, g1, xn);
    // qkv (tf32-rounded store -> feeds tensor-core attention)
    gemm_mma<3><<<dim3(TRIPLE/128, TOK/128), 256, GEMM_SMEM_B>>>(xn, wtqkv, qkv, qkv, TRIPLE, DIMN);
    attn_mma<<<dim3(SEQL/128, NHEADS, 2), 256, ATTN_SMEM>>>(qkv, attn);
    gemm_mma<1><<<dim3(DIMN/128, TOK/128), 256, GEMM_SMEM_B>>>(attn, wtout, x2, x, DIMN, DIMN);
    rmsnorm_kernel<<<TOK, 256>>>(x2, g2, xn);
    gemm_mma<0><<<dim3(FFH/128, TOK/128), 256, GEMM_SMEM_B>>>(xn, wt1, hbuf, hbuf, FFH, DIMN);
    gemm_mma<2><<<dim3(FFH/128, TOK/128), 256, GEMM_SMEM_B>>>(xn, wt3, hbuf, hbuf, FFH, DIMN);
    gemm_mma<1><<<dim3(DIMN/128, TOK/128), 256, GEMM_SMEM_B>>>(hbuf, wt2, out, x2, DIMN, FFH);
}

// round 6
// speedup vs baseline: 3.4104x; 1.1877x over previous
#include <cuda_runtime.h>
#include <math.h>
#include <stdint.h>

#define TOK    4096
#define DIMN   2048
#define TRIPLE 6144
#define FFH    5632
#define NHEADS 16
#define HDIM   128
#define SEQL   2048

// ---------------- scratch (device globals: allocation-free) ----------------
__device__ float g_xn    [(size_t)TOK * DIMN];
__device__ float g_qkv   [(size_t)TOK * TRIPLE];
__device__ float g_attn  [(size_t)TOK * DIMN];
__device__ float g_x2    [(size_t)TOK * DIMN];
__device__ float g_h     [(size_t)TOK * FFH];
// transposed + tf32-rounded weights [N, K]
__device__ float g_wtqkv [(size_t)TRIPLE * DIMN];
__device__ float g_wtout [(size_t)DIMN * DIMN];
__device__ float g_wt1   [(size_t)FFH * DIMN];
__device__ float g_wt3   [(size_t)FFH * DIMN];
__device__ float g_wt2   [(size_t)DIMN * FFH];

// ---------------- helpers ----------------
__device__ __forceinline__ uint32_t smem_u32(const void* p) {
    uint32_t a;
    asm("{ .reg .u64 t; cvta.to.shared.u64 t, %1; cvt.u32.u64 %0, t; }" : "=r"(a) : "l"(p));
    return a;
}
__device__ __forceinline__ float to_tf32(float v) {
    uint32_t r;
    asm("cvt.rna.tf32.f32 %0, %1;" : "=r"(r) : "f"(v));
    return __uint_as_float(r);
}

#define CP16(dst, src) \
    asm volatile("cp.async.cg.shared.global [%0], [%1], 16;" :: "r"(dst), "l"(src))
#define CP_COMMIT() asm volatile("cp.async.commit_group;" ::: "memory")
#define CP_WAIT1()  asm volatile("cp.async.wait_group 1;" ::: "memory")

__device__ __forceinline__ void mma_tf32(float& d0, float& d1, float& d2, float& d3,
                                         uint32_t a0, uint32_t a1, uint32_t a2, uint32_t a3,
                                         uint32_t b0, uint32_t b1) {
    asm volatile(
        "mma.sync.aligned.m16n8k8.row.col.f32.tf32.tf32.f32 "
        "{%0,%1,%2,%3}, {%4,%5,%6,%7}, {%8,%9}, {%0,%1,%2,%3};"
        : "+f"(d0), "+f"(d1), "+f"(d2), "+f"(d3)
        : "r"(a0), "r"(a1), "r"(a2), "r"(a3), "r"(b0), "r"(b1));
}

// ---------------- transpose + tf32 round: in [R, Ccols] -> out [Ccols, R] ----------------
__global__ void __launch_bounds__(256) transpose_round_kernel(const float* __restrict__ in,
                                                              float* __restrict__ out,
                                                              int R, int Ccols) {
    __shared__ float t[32][33];
    const int bx = blockIdx.x * 32;
    const int by = blockIdx.y * 32;
    const int x = threadIdx.x, y = threadIdx.y;
#pragma unroll
    for (int i = 0; i < 32; i += 8)
        t[y + i][x] = in[(size_t)(by + y + i) * Ccols + bx + x];
    __syncthreads();
#pragma unroll
    for (int i = 0; i < 32; i += 8)
        out[(size_t)(bx + y + i) * R + by + x] = to_tf32(t[x][y + i]);
}

// ---------------- RMSNorm (+ tf32 round on output) ----------------
__global__ void __launch_bounds__(256) rmsnorm_kernel(const float* __restrict__ x,
                                                      const float* __restrict__ g,
                                                      float* __restrict__ o) {
    const int t = blockIdx.x;
    const float4* xr = reinterpret_cast<const float4*>(x) + (size_t)t * (DIMN / 4);
    float4* orow     = reinterpret_cast<float4*>(o) + (size_t)t * (DIMN / 4);
    const float4* g4 = reinterpret_cast<const float4*>(g);
    const int i0 = threadIdx.x, i1 = threadIdx.x + 256;
    const float4 v0 = xr[i0], v1 = xr[i1];
    float ss = v0.x*v0.x + v0.y*v0.y + v0.z*v0.z + v0.w*v0.w
             + v1.x*v1.x + v1.y*v1.y + v1.z*v1.z + v1.w*v1.w;
#pragma unroll
    for (int off = 16; off > 0; off >>= 1)
        ss += __shfl_xor_sync(0xffffffffu, ss, off);
    __shared__ float red[8];
    if ((threadIdx.x & 31) == 0) red[threadIdx.x >> 5] = ss;
    __syncthreads();
    const float tot = red[0]+red[1]+red[2]+red[3]+red[4]+red[5]+red[6]+red[7];
    const float r = rsqrtf(tot * (1.0f / DIMN) + 1e-6f);
    const float4 ga = g4[i0], gb = g4[i1];
    float4 o0, o1;
    o0.x = to_tf32(v0.x * r * ga.x); o0.y = to_tf32(v0.y * r * ga.y);
    o0.z = to_tf32(v0.z * r * ga.z); o0.w = to_tf32(v0.w * r * ga.w);
    o1.x = to_tf32(v1.x * r * gb.x); o1.y = to_tf32(v1.y * r * gb.y);
    o1.z = to_tf32(v1.z * r * gb.z); o1.w = to_tf32(v1.w * r * gb.w);
    orow[i0] = o0; orow[i1] = o1;
}

// ---------------- tf32 mma.sync GEMM: C[M,N] = A[M,K] @ Bt[N,K]^T ----------------
#define BSTRIDE 36
#define KT 32
#define NSTAGE 3
#define STAGE_FLOATS (2 * 128 * BSTRIDE)
#define GEMM_SMEM_B (NSTAGE * STAGE_FLOATS * 4)

__device__ __forceinline__ void load_stage(float* st, const float* __restrict__ A,
                                           const float* __restrict__ Bt,
                                           int bm, int bn, int K, int kt, int tid) {
    float* as = st;
    float* bs = st + 128 * BSTRIDE;
#pragma unroll
    for (int t = 0; t < 4; ++t) {
        const int id = t * 256 + tid;
        const int row = id >> 3, c4 = id & 7;
        CP16(smem_u32(as + row * BSTRIDE + c4 * 4),
             A  + (size_t)(bm + row) * K + kt * KT + c4 * 4);
        CP16(smem_u32(bs + row * BSTRIDE + c4 * 4),
             Bt + (size_t)(bn + row) * K + kt * KT + c4 * 4);
    }
}

// EPI: 0 plain, 1 C=acc+aux, 2 C=to_tf32(silu(aux)*acc), 3 C=to_tf32(acc)
template<int EPI>
__global__ void __launch_bounds__(256, 2)
gemm_mma(const float* __restrict__ A, const float* __restrict__ Bt,
         float* __restrict__ C, const float* __restrict__ aux, int N, int K)
{
    extern __shared__ float smf[];
    const int tid = threadIdx.x, lane = tid & 31, wid = tid >> 5;
    const int bm = blockIdx.y << 7, bn = blockIdx.x << 7;
    const int wm = (wid >> 1) * 32, wn = (wid & 1) * 64;
    const int r = lane >> 2, c = lane & 3;

    float acc[2][8][4];
#pragma unroll
    for (int mi = 0; mi < 2; ++mi)
#pragma unroll
        for (int ni = 0; ni < 8; ++ni)
#pragma unroll
            for (int q = 0; q < 4; ++q) acc[mi][ni][q] = 0.0f;

    load_stage(smf, A, Bt, bm, bn, K, 0, tid); CP_COMMIT();
    load_stage(smf + STAGE_FLOATS, A, Bt, bm, bn, K, 1, tid); CP_COMMIT();

    const int nk = K / KT;
    for (int kt = 0; kt < nk; ++kt) {
        const int s = kt % NSTAGE;
        CP_WAIT1();
        __syncthreads();
        const int pf = kt + 2;
        if (pf < nk) {
            load_stage(smf + (pf % NSTAGE) * STAGE_FLOATS, A, Bt, bm, bn, K, pf, tid);
            CP_COMMIT();
        }

        const float* as = smf + s * STAGE_FLOATS;
        const float* bs = as + 128 * BSTRIDE;
#pragma unroll
        for (int k8 = 0; k8 < 4; ++k8) {
            const int kk = k8 * 8 + c;
            uint32_t a[2][4];
#pragma unroll
            for (int mi = 0; mi < 2; ++mi) {
                const float* ap = as + (wm + mi * 16) * BSTRIDE + kk;
                a[mi][0] = __float_as_uint(ap[r * BSTRIDE]);
                a[mi][1] = __float_as_uint(ap[(r + 8) * BSTRIDE]);
                a[mi][2] = __float_as_uint(ap[r * BSTRIDE + 4]);
                a[mi][3] = __float_as_uint(ap[(r + 8) * BSTRIDE + 4]);
            }
#pragma unroll
            for (int ni = 0; ni < 8; ++ni) {
                const float* bp = bs + (wn + ni * 8 + r) * BSTRIDE + kk;
                const uint32_t b0 = __float_as_uint(bp[0]);
                const uint32_t b1 = __float_as_uint(bp[4]);
                mma_tf32(acc[0][ni][0], acc[0][ni][1], acc[0][ni][2], acc[0][ni][3],
                         a[0][0], a[0][1], a[0][2], a[0][3], b0, b1);
                mma_tf32(acc[1][ni][0], acc[1][ni][1], acc[1][ni][2], acc[1][ni][3],
                         a[1][0], a[1][1], a[1][2], a[1][3], b0, b1);
            }
        }
    }

#pragma unroll
    for (int mi = 0; mi < 2; ++mi) {
#pragma unroll
        for (int ni = 0; ni < 8; ++ni) {
            const int row0 = bm + wm + mi * 16 + r;
            const int col  = bn + wn + ni * 8 + c * 2;
#pragma unroll
            for (int half = 0; half < 2; ++half) {
                const int row = row0 + half * 8;
                float vx = acc[mi][ni][half * 2 + 0];
                float vy = acc[mi][ni][half * 2 + 1];
                float* cp = C + (size_t)row * N + col;
                if (EPI == 1) {
                    const float2 a2 = *(const float2*)(aux + (size_t)row * N + col);
                    vx += a2.x; vy += a2.y;
                } else if (EPI == 2) {
                    const float2 g2 = *(const float2*)(aux + (size_t)row * N + col);
                    vx = to_tf32(vx * g2.x / (1.0f + __expf(-g2.x)));
                    vy = to_tf32(vy * g2.y / (1.0f + __expf(-g2.y)));
                } else if (EPI == 3) {
                    vx = to_tf32(vx); vy = to_tf32(vy);
                }
                *(float2*)cp = make_float2(vx, vy);
            }
        }
    }
}

// ---------------- Flash attention on tensor cores (tf32 mma) ----------------
// BQ=128, BKV=64, HD=128, 8 warps (each owns 16 q-rows)
#define QS_OFF 0
#define QS_STR 132
#define KS_OFF (128 * 132)
#define KS_STR 132
#define VT_OFF (KS_OFF + 64 * 132)
#define PS_OFF (VT_OFF + 128 * 64)
#define PS_STR 68
#define ATTN_SMEM ((PS_OFF + 128 * 68) * 4)

__device__ __forceinline__ int vt_idx(int n, int k) {
    return VT_OFF + n * 64 + (k ^ ((n & 7) << 2) ^ ((n >> 3) & 3));
}

__global__ void __launch_bounds__(256, 1)
attn_mma(const float* __restrict__ qkv, float* __restrict__ out)
{
    extern __shared__ float sm[];
    const int qt = blockIdx.x, h = blockIdx.y, b = blockIdx.z;
    const int tid = threadIdx.x, lane = tid & 31, wid = tid >> 5;
    const int r = lane >> 2, c = lane & 3;
    const int q0 = qt * 128;
    const int tb = b * SEQL + q0;
    const int wq = wid * 16;
    const int qcol = h * HDIM, kcol = DIMN + h * HDIM, vcol = 2 * DIMN + h * HDIM;
    const float scale = 0.08838834764831845f;  // 1/sqrt(128)

    // load Q tile [128][128] -> Qs
#pragma unroll
    for (int it = 0; it < 16; ++it) {
        const int idx = it * 256 + tid;
        const int row = idx >> 5, c4 = idx & 31;
        *(float4*)&sm[QS_OFF + row * QS_STR + c4 * 4] =
            *(const float4*)(qkv + (size_t)(tb + row) * TRIPLE + qcol + c4 * 4);
    }

    float m[2] = {-1e30f, -1e30f}, l[2] = {0.0f, 0.0f};
    float acc[16][4];
#pragma unroll
    for (int nt = 0; nt < 16; ++nt)
#pragma unroll
        for (int q = 0; q < 4; ++q) acc[nt][q] = 0.0f;

    const int nkv = 2 * qt + 2;
    for (int kt = 0; kt < nkv; ++kt) {
        __syncthreads();
        const int kb = b * SEQL + kt * 64;
#pragma unroll
        for (int it = 0; it < 8; ++it) {
            const int idx = it * 256 + tid;
            const int row = idx >> 5, c4 = idx & 31;
            *(float4*)&sm[KS_OFF + row * KS_STR + c4 * 4] =
                *(const float4*)(qkv + (size_t)(kb + row) * TRIPLE + kcol + c4 * 4);
        }
#pragma unroll
        for (int it = 0; it < 8; ++it) {
            const int idx = it * 256 + tid;
            const int row = idx >> 5, c4 = idx & 31;
            const float4 v = *(const float4*)(qkv + (size_t)(kb + row) * TRIPLE + vcol + c4 * 4);
            sm[vt_idx(c4 * 4 + 0, row)] = v.x;
            sm[vt_idx(c4 * 4 + 1, row)] = v.y;
            sm[vt_idx(c4 * 4 + 2, row)] = v.z;
            sm[vt_idx(c4 * 4 + 3, row)] = v.w;
        }
        __syncthreads();

        // ---- S = Q K^T (warp: 16x64, K=128) ----
        float s[8][4];
#pragma unroll
        for (int nt = 0; nt < 8; ++nt)
#pragma unroll
            for (int q = 0; q < 4; ++q) s[nt][q] = 0.0f;
#pragma unroll
        for (int k8 = 0; k8 < 16; ++k8) {
            const int kk = k8 * 8 + c;
            const float* ap = sm + QS_OFF + (wq + r) * QS_STR + kk;
            const uint32_t a0 = __float_as_uint(ap[0]);
            const uint32_t a1 = __float_as_uint(ap[8 * QS_STR]);
            const uint32_t a2 = __float_as_uint(ap[4]);
            const uint32_t a3 = __float_as_uint(ap[8 * QS_STR + 4]);
#pragma unroll
            for (int nt = 0; nt < 8; ++nt) {
                const float* bp = sm + KS_OFF + (nt * 8 + r) * KS_STR + kk;
                mma_tf32(s[nt][0], s[nt][1], s[nt][2], s[nt][3],
                         a0, a1, a2, a3,
                         __float_as_uint(bp[0]), __float_as_uint(bp[4]));
            }
        }

        // ---- online softmax ----
        const bool diag = (kt >= 2 * qt);
#pragma unroll
        for (int half = 0; half < 2; ++half) {
            const int qg = q0 + wq + r + 8 * half;
            float rm = -1e30f;
#pragma unroll
            for (int nt = 0; nt < 8; ++nt)
#pragma unroll
                for (int q2 = 0; q2 < 2; ++q2) {
                    float v = s[nt][2 * half + q2] * scale;
                    if (diag && (kt * 64 + nt * 8 + 2 * c + q2 > qg)) v = -1e30f;
                    s[nt][2 * half + q2] = v;
                    rm = fmaxf(rm, v);
                }
            rm = fmaxf(rm, __shfl_xor_sync(0xffffffffu, rm, 1));
            rm = fmaxf(rm, __shfl_xor_sync(0xffffffffu, rm, 2));
            const float mn = fmaxf(m[half], rm);
            const float corr = __expf(m[half] - mn);
            float rs = 0.0f;
#pragma unroll
            for (int nt = 0; nt < 8; ++nt)
#pragma unroll
                for (int q2 = 0; q2 < 2; ++q2) {
                    const float p = __expf(s[nt][2 * half + q2] - mn);
                    s[nt][2 * half + q2] = p;
                    rs += p;
                }
            rs += __shfl_xor_sync(0xffffffffu, rs, 1);
            rs += __shfl_xor_sync(0xffffffffu, rs, 2);
            l[half] = l[half] * corr + rs;
            m[half] = mn;
#pragma unroll
            for (int nt = 0; nt < 16; ++nt) {
                acc[nt][2 * half + 0] *= corr;
                acc[nt][2 * half + 1] *= corr;
            }
#pragma unroll
            for (int nt = 0; nt < 8; ++nt)
                *(float2*)&sm[PS_OFF + (wq + r + 8 * half) * PS_STR + nt * 8 + 2 * c] =
                    make_float2(to_tf32(s[nt][2 * half + 0]), to_tf32(s[nt][2 * half + 1]));
        }
        __syncwarp();

        // ---- O += P V (warp: 16x128, K=64) ----
#pragma unroll
        for (int k8 = 0; k8 < 8; ++k8) {
            const int kk = k8 * 8 + c;
            const float* ap = sm + PS_OFF + (wq + r) * PS_STR + kk;
            const uint32_t a0 = __float_as_uint(ap[0]);
            const uint32_t a1 = __float_as_uint(ap[8 * PS_STR]);
            const uint32_t a2 = __float_as_uint(ap[4]);
            const uint32_t a3 = __float_as_uint(ap[8 * PS_STR + 4]);
#pragma unroll
            for (int nt = 0; nt < 16; ++nt) {
                const uint32_t b0 = __float_as_uint(sm[vt_idx(nt * 8 + r, kk)]);
                const uint32_t b1 = __float_as_uint(sm[vt_idx(nt * 8 + r, kk + 4)]);
                mma_tf32(acc[nt][0], acc[nt][1], acc[nt][2], acc[nt][3],
                         a0, a1, a2, a3, b0, b1);
            }
        }
    }

    // ---- write O (tf32-rounded; feeds w_out GEMM) ----
#pragma unroll
    for (int half = 0; half < 2; ++half) {
        const float inv = 1.0f / l[half];
        const int row = tb + wq + r + 8 * half;
#pragma unroll
        for (int nt = 0; nt < 16; ++nt) {
            const int col = h * HDIM + nt * 8 + 2 * c;
            *(float2*)(out + (size_t)row * DIMN + col) =
                make_float2(to_tf32(acc[nt][2 * half + 0] * inv),
                            to_tf32(acc[nt][2 * half + 1] * inv));
        }
    }
}

// ---------------- host ----------------
extern "C" void kernel_launch(void* const* d_in, const int* in_sizes, int n_in,
                              void* d_out, int out_size) {
    const float* x     = (const float*)d_in[0];
    const float* w_qkv = (const float*)d_in[1];
    const float* w_out = (const float*)d_in[2];
    const float* g1    = (const float*)d_in[3];
    const float* g2    = (const float*)d_in[4];
    const float* w1    = (const float*)d_in[5];
    const float* w3    = (const float*)d_in[6];
    const float* w2    = (const float*)d_in[7];
    float* out = (float*)d_out;
    (void)in_sizes; (void)n_in; (void)out_size;

    float *xn, *qkv, *attn, *x2, *hbuf;
    float *wtqkv, *wtout, *wt1, *wt3, *wt2;
    cudaGetSymbolAddress((void**)&xn,    g_xn);
    cudaGetSymbolAddress((void**)&qkv,   g_qkv);
    cudaGetSymbolAddress((void**)&attn,  g_attn);
    cudaGetSymbolAddress((void**)&x2,    g_x2);
    cudaGetSymbolAddress((void**)&hbuf,  g_h);
    cudaGetSymbolAddress((void**)&wtqkv, g_wtqkv);
    cudaGetSymbolAddress((void**)&wtout, g_wtout);
    cudaGetSymbolAddress((void**)&wt1,   g_wt1);
    cudaGetSymbolAddress((void**)&wt3,   g_wt3);
    cudaGetSymbolAddress((void**)&wt2,   g_wt2);

    cudaFuncSetAttribute(attn_mma,
                         cudaFuncAttributeMaxDynamicSharedMemorySize, ATTN_SMEM);
    cudaFuncSetAttribute(gemm_mma<0>,
                         cudaFuncAttributeMaxDynamicSharedMemorySize, GEMM_SMEM_B);
    cudaFuncSetAttribute(gemm_mma<1>,
                         cudaFuncAttributeMaxDynamicSharedMemorySize, GEMM_SMEM_B);
    cudaFuncSetAttribute(gemm_mma<2>,
                         cudaFuncAttributeMaxDynamicSharedMemorySize, GEMM_SMEM_B);
    cudaFuncSetAttribute(gemm_mma<3>,
                         cudaFuncAttributeMaxDynamicSharedMemorySize, GEMM_SMEM_B);

    const dim3 tb(32, 8);
    transpose_round_kernel<<<dim3(TRIPLE/32, DIMN/32), tb>>>(w_qkv, wtqkv, DIMN, TRIPLE);
    transpose_round_kernel<<<dim3(DIMN/32,  DIMN/32), tb>>>(w_out, wtout, DIMN, DIMN);
    transpose_round_kernel<<<dim3(FFH/32,   DIMN/32), tb>>>(w1,    wt1,   DIMN, FFH);
    transpose_round_kernel<<<dim3(FFH/32,   DIMN/32), tb>>>(w3,    wt3,   DIMN, FFH);
    transpose_round_kernel<<<dim3(DIMN/32,  FFH/32),  tb>>>(w2,    wt2,   FFH,  DIMN);

    rmsnorm_kernel<<<TOK, 256>>>(x, g1, xn);
    gemm_mma<3><<<dim3(TRIPLE/128, TOK/128), 256, GEMM_SMEM_B>>>(xn, wtqkv, qkv, qkv, TRIPLE, DIMN);
    attn_mma<<<dim3(SEQL/128, NHEADS, 2), 256, ATTN_SMEM>>>(qkv, attn);
    gemm_mma<1><<<dim3(DIMN/128, TOK/128), 256, GEMM_SMEM_B>>>(attn, wtout, x2, x, DIMN, DIMN);
    rmsnorm_kernel<<<TOK, 256>>>(x2, g2, xn);
    gemm_mma<0><<<dim3(FFH/128, TOK/128), 256, GEMM_SMEM_B>>>(xn, wt1, hbuf, hbuf, FFH, DIMN);
    gemm_mma<2><<<dim3(FFH/128, TOK/128), 256, GEMM_SMEM_B>>>(xn, wt3, hbuf, hbuf, FFH, DIMN);
    gemm_mma<1><<<dim3(DIMN/128, TOK/128), 256, GEMM_SMEM_B>>>(hbuf, wt2, out, x2, DIMN, FFH);
}

// round 7
// speedup vs baseline: 3.4980x; 1.0257x over previous
#include <cuda_runtime.h>
#include <math.h>
#include <stdint.h>

#define TOK    4096
#define DIMN   2048
#define TRIPLE 6144
#define FFH    5632
#define NHEADS 16
#define HDIM   128
#define SEQL   2048

// ---------------- scratch (device globals: allocation-free) ----------------
__device__ float g_xn    [(size_t)TOK * DIMN];
__device__ float g_qkv   [(size_t)TOK * TRIPLE];
__device__ float g_attn  [(size_t)TOK * DIMN];
__device__ float g_x2    [(size_t)TOK * DIMN];
__device__ float g_h     [(size_t)TOK * FFH];
// transposed + tf32-rounded weights [N, K]
__device__ float g_wtqkv [(size_t)TRIPLE * DIMN];
__device__ float g_wtout [(size_t)DIMN * DIMN];
__device__ float g_wt13  [(size_t)2 * FFH * DIMN];   // interleaved w1/w3
__device__ float g_wt2   [(size_t)DIMN * FFH];

// ---------------- helpers ----------------
__device__ __forceinline__ uint32_t smem_u32(const void* p) {
    uint32_t a;
    asm("{ .reg .u64 t; cvta.to.shared.u64 t, %1; cvt.u32.u64 %0, t; }" : "=r"(a) : "l"(p));
    return a;
}
__device__ __forceinline__ float to_tf32(float v) {
    uint32_t r;
    asm("cvt.rna.tf32.f32 %0, %1;" : "=r"(r) : "f"(v));
    return __uint_as_float(r);
}

#define CP16(dst, src) \
    asm volatile("cp.async.cg.shared.global [%0], [%1], 16;" :: "r"(dst), "l"(src))
#define CP_COMMIT() asm volatile("cp.async.commit_group;" ::: "memory")
#define CP_WAIT1()  asm volatile("cp.async.wait_group 1;" ::: "memory")

__device__ __forceinline__ void mma_tf32(float& d0, float& d1, float& d2, float& d3,
                                         uint32_t a0, uint32_t a1, uint32_t a2, uint32_t a3,
                                         uint32_t b0, uint32_t b1) {
    asm volatile(
        "mma.sync.aligned.m16n8k8.row.col.f32.tf32.tf32.f32 "
        "{%0,%1,%2,%3}, {%4,%5,%6,%7}, {%8,%9}, {%0,%1,%2,%3};"
        : "+f"(d0), "+f"(d1), "+f"(d2), "+f"(d3)
        : "r"(a0), "r"(a1), "r"(a2), "r"(a3), "r"(b0), "r"(b1));
}

// ---------------- transpose + tf32 round ----------------
// out[(col*rmul + radd) * R + row] = to_tf32(in[row * Ccols + col])
__global__ void __launch_bounds__(256) transpose_round_kernel(const float* __restrict__ in,
                                                              float* __restrict__ out,
                                                              int R, int Ccols,
                                                              int rmul, int radd) {
    __shared__ float t[32][33];
    const int bx = blockIdx.x * 32;
    const int by = blockIdx.y * 32;
    const int x = threadIdx.x, y = threadIdx.y;
#pragma unroll
    for (int i = 0; i < 32; i += 8)
        t[y + i][x] = in[(size_t)(by + y + i) * Ccols + bx + x];
    __syncthreads();
#pragma unroll
    for (int i = 0; i < 32; i += 8)
        out[(size_t)((bx + y + i) * rmul + radd) * R + by + x] = to_tf32(t[x][y + i]);
}

// ---------------- RMSNorm (+ tf32 round on output) ----------------
__global__ void __launch_bounds__(256) rmsnorm_kernel(const float* __restrict__ x,
                                                      const float* __restrict__ g,
                                                      float* __restrict__ o) {
    const int t = blockIdx.x;
    const float4* xr = reinterpret_cast<const float4*>(x) + (size_t)t * (DIMN / 4);
    float4* orow     = reinterpret_cast<float4*>(o) + (size_t)t * (DIMN / 4);
    const float4* g4 = reinterpret_cast<const float4*>(g);
    const int i0 = threadIdx.x, i1 = threadIdx.x + 256;
    const float4 v0 = xr[i0], v1 = xr[i1];
    float ss = v0.x*v0.x + v0.y*v0.y + v0.z*v0.z + v0.w*v0.w
             + v1.x*v1.x + v1.y*v1.y + v1.z*v1.z + v1.w*v1.w;
#pragma unroll
    for (int off = 16; off > 0; off >>= 1)
        ss += __shfl_xor_sync(0xffffffffu, ss, off);
    __shared__ float red[8];
    if ((threadIdx.x & 31) == 0) red[threadIdx.x >> 5] = ss;
    __syncthreads();
    const float tot = red[0]+red[1]+red[2]+red[3]+red[4]+red[5]+red[6]+red[7];
    const float r = rsqrtf(tot * (1.0f / DIMN) + 1e-6f);
    const float4 ga = g4[i0], gb = g4[i1];
    float4 o0, o1;
    o0.x = to_tf32(v0.x * r * ga.x); o0.y = to_tf32(v0.y * r * ga.y);
    o0.z = to_tf32(v0.z * r * ga.z); o0.w = to_tf32(v0.w * r * ga.w);
    o1.x = to_tf32(v1.x * r * gb.x); o1.y = to_tf32(v1.y * r * gb.y);
    o1.z = to_tf32(v1.z * r * gb.z); o1.w = to_tf32(v1.w * r * gb.w);
    orow[i0] = o0; orow[i1] = o1;
}

// ---------------- tf32 mma.sync GEMM: C[M,N] = A[M,K] @ Bt[N,K]^T ----------------
#define BSTRIDE 36
#define KT 32
#define NSTAGE 3
#define STAGE_FLOATS (2 * 128 * BSTRIDE)
#define GEMM_SMEM_B (NSTAGE * STAGE_FLOATS * 4)

__device__ __forceinline__ void load_stage(float* st, const float* __restrict__ A,
                                           const float* __restrict__ Bt,
                                           int bm, int bn, int K, int kt, int tid) {
    float* as = st;
    float* bs = st + 128 * BSTRIDE;
#pragma unroll
    for (int t = 0; t < 4; ++t) {
        const int id = t * 256 + tid;
        const int row = id >> 3, c4 = id & 7;
        CP16(smem_u32(as + row * BSTRIDE + c4 * 4),
             A  + (size_t)(bm + row) * K + kt * KT + c4 * 4);
        CP16(smem_u32(bs + row * BSTRIDE + c4 * 4),
             Bt + (size_t)(bn + row) * K + kt * KT + c4 * 4);
    }
}

// EPI: 1 C=acc+aux, 3 C=to_tf32(acc), 4 fused swiglu: C[row][col/2]=to_tf32(silu(vx)*vy)
template<int EPI>
__global__ void __launch_bounds__(256, 2)
gemm_mma(const float* __restrict__ A, const float* __restrict__ Bt,
         float* __restrict__ C, const float* __restrict__ aux, int N, int K)
{
    extern __shared__ float smf[];
    const int tid = threadIdx.x, lane = tid & 31, wid = tid >> 5;
    const int bm = blockIdx.y << 7, bn = blockIdx.x << 7;
    const int wm = (wid >> 1) * 32, wn = (wid & 1) * 64;
    const int r = lane >> 2, c = lane & 3;

    float acc[2][8][4];
#pragma unroll
    for (int mi = 0; mi < 2; ++mi)
#pragma unroll
        for (int ni = 0; ni < 8; ++ni)
#pragma unroll
            for (int q = 0; q < 4; ++q) acc[mi][ni][q] = 0.0f;

    load_stage(smf, A, Bt, bm, bn, K, 0, tid); CP_COMMIT();
    load_stage(smf + STAGE_FLOATS, A, Bt, bm, bn, K, 1, tid); CP_COMMIT();

    const int nk = K / KT;
    for (int kt = 0; kt < nk; ++kt) {
        const int s = kt % NSTAGE;
        CP_WAIT1();
        __syncthreads();
        const int pf = kt + 2;
        if (pf < nk) {
            load_stage(smf + (pf % NSTAGE) * STAGE_FLOATS, A, Bt, bm, bn, K, pf, tid);
            CP_COMMIT();
        }

        const float* as = smf + s * STAGE_FLOATS;
        const float* bs = as + 128 * BSTRIDE;
#pragma unroll
        for (int k8 = 0; k8 < 4; ++k8) {
            const int kk = k8 * 8 + c;
            uint32_t a[2][4];
#pragma unroll
            for (int mi = 0; mi < 2; ++mi) {
                const float* ap = as + (wm + mi * 16) * BSTRIDE + kk;
                a[mi][0] = __float_as_uint(ap[r * BSTRIDE]);
                a[mi][1] = __float_as_uint(ap[(r + 8) * BSTRIDE]);
                a[mi][2] = __float_as_uint(ap[r * BSTRIDE + 4]);
                a[mi][3] = __float_as_uint(ap[(r + 8) * BSTRIDE + 4]);
            }
#pragma unroll
            for (int ni = 0; ni < 8; ++ni) {
                const float* bp = bs + (wn + ni * 8 + r) * BSTRIDE + kk;
                const uint32_t b0 = __float_as_uint(bp[0]);
                const uint32_t b1 = __float_as_uint(bp[4]);
                mma_tf32(acc[0][ni][0], acc[0][ni][1], acc[0][ni][2], acc[0][ni][3],
                         a[0][0], a[0][1], a[0][2], a[0][3], b0, b1);
                mma_tf32(acc[1][ni][0], acc[1][ni][1], acc[1][ni][2], acc[1][ni][3],
                         a[1][0], a[1][1], a[1][2], a[1][3], b0, b1);
            }
        }
    }

#pragma unroll
    for (int mi = 0; mi < 2; ++mi) {
#pragma unroll
        for (int ni = 0; ni < 8; ++ni) {
            const int row0 = bm + wm + mi * 16 + r;
            const int col  = bn + wn + ni * 8 + c * 2;
#pragma unroll
            for (int half = 0; half < 2; ++half) {
                const int row = row0 + half * 8;
                float vx = acc[mi][ni][half * 2 + 0];
                float vy = acc[mi][ni][half * 2 + 1];
                if (EPI == 1) {
                    const float2 a2 = *(const float2*)(aux + (size_t)row * N + col);
                    vx += a2.x; vy += a2.y;
                    *(float2*)(C + (size_t)row * N + col) = make_float2(vx, vy);
                } else if (EPI == 3) {
                    *(float2*)(C + (size_t)row * N + col) =
                        make_float2(to_tf32(vx), to_tf32(vy));
                } else if (EPI == 4) {
                    // vx = gate (w1), vy = up (w3); output col = col/2 in [0, FFH)
                    const float hval = to_tf32(vy * vx / (1.0f + __expf(-vx)));
                    C[(size_t)row * N + (col >> 1)] = hval;
                }
            }
        }
    }
}

// ---------------- Flash attention on tensor cores (tf32 mma) ----------------
// BQ=128, BKV=64, HD=128, 8 warps; K/V register-prefetch pipeline
#define QS_OFF 0
#define QS_STR 132
#define KS_OFF (128 * 132)
#define KS_STR 132
#define VT_OFF (KS_OFF + 64 * 132)
#define PS_OFF (VT_OFF + 128 * 64)
#define PS_STR 68
#define ATTN_SMEM ((PS_OFF + 128 * 68) * 4)

__device__ __forceinline__ int vt_idx(int n, int k) {
    return VT_OFF + n * 64 + (k ^ ((n & 7) << 2) ^ ((n >> 3) & 3));
}

__global__ void __launch_bounds__(256, 1)
attn_mma(const float* __restrict__ qkv, float* __restrict__ out)
{
    extern __shared__ float sm[];
    const int qt = blockIdx.x, h = blockIdx.y, b = blockIdx.z;
    const int tid = threadIdx.x, lane = tid & 31, wid = tid >> 5;
    const int r = lane >> 2, c = lane & 3;
    const int q0 = qt * 128;
    const int tb = b * SEQL + q0;
    const int wq = wid * 16;
    const int qcol = h * HDIM, kcol = DIMN + h * HDIM, vcol = 2 * DIMN + h * HDIM;
    const float scale = 0.08838834764831845f;  // 1/sqrt(128)

    // load Q tile [128][128] -> Qs
#pragma unroll
    for (int it = 0; it < 16; ++it) {
        const int idx = it * 256 + tid;
        const int row = idx >> 5, c4 = idx & 31;
        *(float4*)&sm[QS_OFF + row * QS_STR + c4 * 4] =
            *(const float4*)(qkv + (size_t)(tb + row) * TRIPLE + qcol + c4 * 4);
    }

    // prefetch K/V tile 0 into registers (thread: rows it*8+wid, cols lane*4..+3)
    float4 kreg[8], vreg[8];
    {
        const int kb = b * SEQL;
#pragma unroll
        for (int it = 0; it < 8; ++it) {
            const int row = kb + it * 8 + wid;
            kreg[it] = *(const float4*)(qkv + (size_t)row * TRIPLE + kcol + lane * 4);
            vreg[it] = *(const float4*)(qkv + (size_t)row * TRIPLE + vcol + lane * 4);
        }
    }

    float m[2] = {-1e30f, -1e30f}, l[2] = {0.0f, 0.0f};
    float acc[16][4];
#pragma unroll
    for (int nt = 0; nt < 16; ++nt)
#pragma unroll
        for (int q = 0; q < 4; ++q) acc[nt][q] = 0.0f;

    const int nkv = 2 * qt + 2;
    for (int kt = 0; kt < nkv; ++kt) {
        __syncthreads();   // prior tile consumed / Qs visible on first iter
        // store prefetched K/V to SMEM
#pragma unroll
        for (int it = 0; it < 8; ++it) {
            const int row = it * 8 + wid;
            *(float4*)&sm[KS_OFF + row * KS_STR + lane * 4] = kreg[it];
            sm[vt_idx(lane * 4 + 0, row)] = vreg[it].x;
            sm[vt_idx(lane * 4 + 1, row)] = vreg[it].y;
            sm[vt_idx(lane * 4 + 2, row)] = vreg[it].z;
            sm[vt_idx(lane * 4 + 3, row)] = vreg[it].w;
        }
        // prefetch next tile (latency hidden behind S/softmax/PV below)
        if (kt + 1 < nkv) {
            const int kb2 = b * SEQL + (kt + 1) * 64;
#pragma unroll
            for (int it = 0; it < 8; ++it) {
                const int row = kb2 + it * 8 + wid;
                kreg[it] = *(const float4*)(qkv + (size_t)row * TRIPLE + kcol + lane * 4);
                vreg[it] = *(const float4*)(qkv + (size_t)row * TRIPLE + vcol + lane * 4);
            }
        }
        __syncthreads();

        // ---- S = Q K^T (warp: 16x64, K=128) ----
        float s[8][4];
#pragma unroll
        for (int nt = 0; nt < 8; ++nt)
#pragma unroll
            for (int q = 0; q < 4; ++q) s[nt][q] = 0.0f;
#pragma unroll
        for (int k8 = 0; k8 < 16; ++k8) {
            const int kk = k8 * 8 + c;
            const float* ap = sm + QS_OFF + (wq + r) * QS_STR + kk;
            const uint32_t a0 = __float_as_uint(ap[0]);
            const uint32_t a1 = __float_as_uint(ap[8 * QS_STR]);
            const uint32_t a2 = __float_as_uint(ap[4]);
            const uint32_t a3 = __float_as_uint(ap[8 * QS_STR + 4]);
#pragma unroll
            for (int nt = 0; nt < 8; ++nt) {
                const float* bp = sm + KS_OFF + (nt * 8 + r) * KS_STR + kk;
                mma_tf32(s[nt][0], s[nt][1], s[nt][2], s[nt][3],
                         a0, a1, a2, a3,
                         __float_as_uint(bp[0]), __float_as_uint(bp[4]));
            }
        }

        // ---- online softmax ----
        const bool diag = (kt >= 2 * qt);
#pragma unroll
        for (int half = 0; half < 2; ++half) {
            const int qg = q0 + wq + r + 8 * half;
            float rm = -1e30f;
#pragma unroll
            for (int nt = 0; nt < 8; ++nt)
#pragma unroll
                for (int q2 = 0; q2 < 2; ++q2) {
                    float v = s[nt][2 * half + q2] * scale;
                    if (diag && (kt * 64 + nt * 8 + 2 * c + q2 > qg)) v = -1e30f;
                    s[nt][2 * half + q2] = v;
                    rm = fmaxf(rm, v);
                }
            rm = fmaxf(rm, __shfl_xor_sync(0xffffffffu, rm, 1));
            rm = fmaxf(rm, __shfl_xor_sync(0xffffffffu, rm, 2));
            const float mn = fmaxf(m[half], rm);
            const float corr = __expf(m[half] - mn);
            float rs = 0.0f;
#pragma unroll
            for (int nt = 0; nt < 8; ++nt)
#pragma unroll
                for (int q2 = 0; q2 < 2; ++q2) {
                    const float p = __expf(s[nt][2 * half + q2] - mn);
                    s[nt][2 * half + q2] = p;
                    rs += p;
                }
            rs += __shfl_xor_sync(0xffffffffu, rs, 1);
            rs += __shfl_xor_sync(0xffffffffu, rs, 2);
            l[half] = l[half] * corr + rs;
            m[half] = mn;
#pragma unroll
            for (int nt = 0; nt < 16; ++nt) {
                acc[nt][2 * half + 0] *= corr;
                acc[nt][2 * half + 1] *= corr;
            }
#pragma unroll
            for (int nt = 0; nt < 8; ++nt)
                *(float2*)&sm[PS_OFF + (wq + r + 8 * half) * PS_STR + nt * 8 + 2 * c] =
                    make_float2(to_tf32(s[nt][2 * half + 0]), to_tf32(s[nt][2 * half + 1]));
        }
        __syncwarp();

        // ---- O += P V (warp: 16x128, K=64) ----
#pragma unroll
        for (int k8 = 0; k8 < 8; ++k8) {
            const int kk = k8 * 8 + c;
            const float* ap = sm + PS_OFF + (wq + r) * PS_STR + kk;
            const uint32_t a0 = __float_as_uint(ap[0]);
            const uint32_t a1 = __float_as_uint(ap[8 * PS_STR]);
            const uint32_t a2 = __float_as_uint(ap[4]);
            const uint32_t a3 = __float_as_uint(ap[8 * PS_STR + 4]);
#pragma unroll
            for (int nt = 0; nt < 16; ++nt) {
                const uint32_t b0 = __float_as_uint(sm[vt_idx(nt * 8 + r, kk)]);
                const uint32_t b1 = __float_as_uint(sm[vt_idx(nt * 8 + r, kk + 4)]);
                mma_tf32(acc[nt][0], acc[nt][1], acc[nt][2], acc[nt][3],
                         a0, a1, a2, a3, b0, b1);
            }
        }
    }

    // ---- write O (tf32-rounded; feeds w_out GEMM) ----
#pragma unroll
    for (int half = 0; half < 2; ++half) {
        const float inv = 1.0f / l[half];
        const int row = tb + wq + r + 8 * half;
#pragma unroll
        for (int nt = 0; nt < 16; ++nt) {
            const int col = h * HDIM + nt * 8 + 2 * c;
            *(float2*)(out + (size_t)row * DIMN + col) =
                make_float2(to_tf32(acc[nt][2 * half + 0] * inv),
                            to_tf32(acc[nt][2 * half + 1] * inv));
        }
    }
}

// ---------------- host ----------------
extern "C" void kernel_launch(void* const* d_in, const int* in_sizes, int n_in,
                              void* d_out, int out_size) {
    const float* x     = (const float*)d_in[0];
    const float* w_qkv = (const float*)d_in[1];
    const float* w_out = (const float*)d_in[2];
    const float* g1    = (const float*)d_in[3];
    const float* g2    = (const float*)d_in[4];
    const float* w1    = (const float*)d_in[5];
    const float* w3    = (const float*)d_in[6];
    const float* w2    = (const float*)d_in[7];
    float* out = (float*)d_out;
    (void)in_sizes; (void)n_in; (void)out_size;

    float *xn, *qkv, *attn, *x2, *hbuf;
    float *wtqkv, *wtout, *wt13, *wt2;
    cudaGetSymbolAddress((void**)&xn,    g_xn);
    cudaGetSymbolAddress((void**)&qkv,   g_qkv);
    cudaGetSymbolAddress((void**)&attn,  g_attn);
    cudaGetSymbolAddress((void**)&x2,    g_x2);
    cudaGetSymbolAddress((void**)&hbuf,  g_h);
    cudaGetSymbolAddress((void**)&wtqkv, g_wtqkv);
    cudaGetSymbolAddress((void**)&wtout, g_wtout);
    cudaGetSymbolAddress((void**)&wt13,  g_wt13);
    cudaGetSymbolAddress((void**)&wt2,   g_wt2);

    cudaFuncSetAttribute(attn_mma,
                         cudaFuncAttributeMaxDynamicSharedMemorySize, ATTN_SMEM);
    cudaFuncSetAttribute(gemm_mma<1>,
                         cudaFuncAttributeMaxDynamicSharedMemorySize, GEMM_SMEM_B);
    cudaFuncSetAttribute(gemm_mma<3>,
                         cudaFuncAttributeMaxDynamicSharedMemorySize, GEMM_SMEM_B);
    cudaFuncSetAttribute(gemm_mma<4>,
                         cudaFuncAttributeMaxDynamicSharedMemorySize, GEMM_SMEM_B);

    const dim3 tb(32, 8);
    transpose_round_kernel<<<dim3(TRIPLE/32, DIMN/32), tb>>>(w_qkv, wtqkv, DIMN, TRIPLE, 1, 0);
    transpose_round_kernel<<<dim3(DIMN/32,  DIMN/32), tb>>>(w_out, wtout, DIMN, DIMN, 1, 0);
    transpose_round_kernel<<<dim3(FFH/32,   DIMN/32), tb>>>(w1,    wt13,  DIMN, FFH, 2, 0);
    transpose_round_kernel<<<dim3(FFH/32,   DIMN/32), tb>>>(w3,    wt13,  DIMN, FFH, 2, 1);
    transpose_round_kernel<<<dim3(DIMN/32,  FFH/32),  tb>>>(w2,    wt2,   FFH,  DIMN, 1, 0);

    rmsnorm_kernel<<<TOK, 256>>>(x, g1, xn);
    // qkv (tf32-rounded store -> feeds tensor-core attention)
    gemm_mma<3><<<dim3(TRIPLE/128, TOK/128), 256, GEMM_SMEM_B>>>(xn, wtqkv, qkv, qkv, TRIPLE, DIMN);
    attn_mma<<<dim3(SEQL/128, NHEADS, 2), 256, ATTN_SMEM>>>(qkv, attn);
    gemm_mma<1><<<dim3(DIMN/128, TOK/128), 256, GEMM_SMEM_B>>>(attn, wtout, x2, x, DIMN, DIMN);
    rmsnorm_kernel<<<TOK, 256>>>(x2, g2, xn);
    // fused swiglu: h = silu(xn@w1) * (xn@w3), interleaved weights, N'=2*FFH
    gemm_mma<4><<<dim3(2*FFH/128, TOK/128), 256, GEMM_SMEM_B>>>(xn, wt13, hbuf, hbuf, FFH, DIMN);
    // out = h @ w2 + x2
    gemm_mma<1><<<dim3(DIMN/128, TOK/128), 256, GEMM_SMEM_B>>>(hbuf, wt2, out, x2, DIMN, FFH);
}